// round 12
// baseline (speedup 1.0000x reference)
#include <cuda_runtime.h>
#include <cuda_fp16.h>
#include <cstdint>

constexpr int NB  = 8;
constexpr int CH  = 512;
constexpr int HW  = 4096;
constexpr int HW2 = 2048;
constexpr int CO  = 256;

// ---------------- device scratch ----------------
__device__ __align__(256) float g_S [(size_t)NB * HW2 * HW2];

__device__ __align__(256) __half g_qTh[(size_t)NB * HW * CH];
__device__ __align__(256) __half g_kTh[(size_t)NB * HW * CH];
__device__ __align__(256) __half g_vTh[(size_t)NB * HW * CH];
__device__ __align__(256) __half g_Wph[CO * CH], g_Wpl[CO * CH];
__device__ __align__(256) __half g_Wth[CO * CH], g_Wtl[CO * CH];
__device__ __align__(256) __half g_Wgh[CO * CH], g_Wgl[CO * CH];
__device__ __align__(256) __half g_Wmh[CH * CO], g_Wml[CH * CO];
__device__ __align__(256) __half g_gh [(size_t)NB * CH * HW2];
__device__ __align__(256) __half g_pTh[(size_t)NB * HW2 * CH], g_pTl[(size_t)NB * HW2 * CH];
__device__ __align__(256) __half g_tTh[(size_t)NB * HW2 * CH];
__device__ __align__(256) __half g_Sh [(size_t)NB * HW2 * HW2];
__device__ __align__(256) __half g_y3h[(size_t)NB * HW * CO];

// ---------------- helpers ----------------
__device__ __forceinline__ uint32_t s2u(const void* p) {
    uint32_t a;
    asm("{ .reg .u64 t; cvta.to.shared.u64 t, %1; cvt.u32.u64 %0, t; }" : "=r"(a) : "l"(p));
    return a;
}
__device__ __forceinline__ void hsplit(float v, __half& h, __half& l) {
    h = __float2half(v);
    l = __float2half(v - __half2float(h));
}
__device__ __forceinline__ void ldsm4(uint32_t* r, uint32_t addr) {
    asm volatile("ldmatrix.sync.aligned.m8n8.x4.shared.b16 {%0,%1,%2,%3}, [%4];"
                 : "=r"(r[0]), "=r"(r[1]), "=r"(r[2]), "=r"(r[3]) : "r"(addr));
}
__device__ __forceinline__ void mma16816(float* d, const uint32_t* a, uint32_t b0, uint32_t b1) {
    asm volatile("mma.sync.aligned.m16n8k16.row.col.f32.f16.f16.f32 "
                 "{%0,%1,%2,%3}, {%4,%5,%6,%7}, {%8,%9}, {%0,%1,%2,%3};"
                 : "+f"(d[0]), "+f"(d[1]), "+f"(d[2]), "+f"(d[3])
                 : "r"(a[0]), "r"(a[1]), "r"(a[2]), "r"(a[3]), "r"(b0), "r"(b1));
}
__device__ __forceinline__ void cpasync16(uint32_t s, const void* g) {
    asm volatile("cp.async.cg.shared.global [%0], [%1], 16;" :: "r"(s), "l"(g));
}
#define CP_COMMIT() asm volatile("cp.async.commit_group;" ::: "memory")
#define CP_WAIT0()  asm volatile("cp.async.wait_group 0;" ::: "memory")

// BK=64: rows of 128 B (64 fp16), 8 chunks of 16 B, swizzle c ^= (row & 7).
// Stage layout: Ah @0 (16 KB), Al @16384 (TERMS==2), Bh @BOFF (16 KB).
// TERMS==2: BOFF=32768, stride 49152 (2 stages = 96 KB)
// TERMS==1: BOFF=16384, stride 32768 (2 stages = 64 KB)
template <int TERMS>
__device__ __forceinline__ void load_stage(uint32_t sbase,
    const __half* pAh, const __half* pAl, const __half* pBh,
    int Ktot, int kofs, int tid)
{
    constexpr uint32_t BOFF = (TERMS == 2) ? 32768u : 16384u;
    const int row = tid >> 1;                 // 0..127
    const int c0 = (tid & 1) * 4;             // 0 or 4
    const long long gofs = (long long)row * Ktot + kofs;
    #pragma unroll
    for (int s = 0; s < 4; s++) {
        const int c = c0 + s;
        const uint32_t soff = row * 128 + ((c ^ (row & 7)) << 4);
        cpasync16(sbase +         soff, pAh + gofs + c * 8);
        if (TERMS == 2)
            cpasync16(sbase + 16384 + soff, pAl + gofs + c * 8);
        cpasync16(sbase + BOFF  + soff, pBh + gofs + c * 8);
    }
}

// ---------------------------------------------------------------------------
// Split-fp16 tensor-core GEMM (mma.sync), BK=64, 2-stage cp.async pipeline:
// ONE barrier per 64-K chunk; next chunk's loads issued before the MMA run.
// D(128x128 fp32 tile) = (Ah[+Al])(MxK) @ Bh^T(NxK), fp16 K-major.
// TERMS: 2 = hh + lh; 1 = hh only.
// EPI: 0 fp32 store | 1 row-major hi | 2 fp32+r1+r2 | 3 transposed hi+lo (pT)
//      5 transposed hi (tT) | 4 transposed hi parity-grouped (y3)
// ---------------------------------------------------------------------------
template <int EPI, int TERMS>
__global__ void __launch_bounds__(256, 2) mma_gemm(
    const __half* __restrict__ Ah, const __half* __restrict__ Al,
    const __half* __restrict__ Bh,
    float* __restrict__ C, __half* __restrict__ Ch, __half* __restrict__ Cl,
    int Ktot, int ldc,
    long long sA, long long sB, long long sC,
    const float* __restrict__ r1, const float* __restrict__ r2)
{
    extern __shared__ __align__(1024) char sm[];
    constexpr uint32_t BOFF   = (TERMS == 2) ? 32768u : 16384u;
    constexpr uint32_t STRIDE = (TERMS == 2) ? 49152u : 32768u;
    const int tid = threadIdx.x;
    const int wid = tid >> 5, lane = tid & 31;
    const uint32_t sb = s2u(sm);

    const int m0 = blockIdx.y * 128;
    const int n0 = blockIdx.x * 128;
    const long long bz = blockIdx.z;

    const __half* pAh = Ah + bz * sA + (long long)m0 * Ktot;
    const __half* pAl = (TERMS == 2) ? (Al + bz * sA + (long long)m0 * Ktot) : nullptr;
    const __half* pBh = Bh + bz * sB + (long long)n0 * Ktot;

    const int wm = (wid >> 1) * 32;
    const int wn = (wid & 1) * 64;

    float acc[2][8][4];
    #pragma unroll
    for (int i = 0; i < 2; i++)
        #pragma unroll
        for (int j = 0; j < 8; j++)
            #pragma unroll
            for (int t = 0; t < 4; t++) acc[i][j][t] = 0.0f;

    const int nch = Ktot >> 6;
    load_stage<TERMS>(sb, pAh, pAl, pBh, Ktot, 0, tid);
    CP_COMMIT();

    for (int ic = 0; ic < nch; ic++) {
        CP_WAIT0();
        __syncthreads();
        if (ic + 1 < nch) {
            load_stage<TERMS>(sb + ((ic + 1) & 1) * STRIDE, pAh, pAl, pBh,
                              Ktot, (ic + 1) << 6, tid);
            CP_COMMIT();
        }
        const uint32_t st = sb + (ic & 1) * STRIDE;
        #pragma unroll
        for (int kk = 0; kk < 64; kk += 16) {
            const int kc = (kk >> 3) + (lane >> 4);   // 0..7
            uint32_t a_h[2][4], a_l[2][4], b_all[4][4];
            #pragma unroll
            for (int mi = 0; mi < 2; mi++) {
                const int row = wm + mi * 16 + (lane & 15);
                const uint32_t ad = st + row * 128 + ((kc ^ (row & 7)) << 4);
                ldsm4(a_h[mi], ad);
                if (TERMS == 2) ldsm4(a_l[mi], ad + 16384);
            }
            #pragma unroll
            for (int jj = 0; jj < 4; jj++) {
                const int row = wn + jj * 16 + (lane & 15);
                const uint32_t bd = st + BOFF + row * 128 + ((kc ^ (row & 7)) << 4);
                ldsm4(b_all[jj], bd);
            }
            // hi pass: 16 independent MMAs
            #pragma unroll
            for (int jj = 0; jj < 4; jj++)
                #pragma unroll
                for (int mi = 0; mi < 2; mi++) {
                    mma16816(acc[mi][jj * 2],     a_h[mi], b_all[jj][0], b_all[jj][2]);
                    mma16816(acc[mi][jj * 2 + 1], a_h[mi], b_all[jj][1], b_all[jj][3]);
                }
            // lo pass
            if (TERMS == 2) {
                #pragma unroll
                for (int jj = 0; jj < 4; jj++)
                    #pragma unroll
                    for (int mi = 0; mi < 2; mi++) {
                        mma16816(acc[mi][jj * 2],     a_l[mi], b_all[jj][0], b_all[jj][2]);
                        mma16816(acc[mi][jj * 2 + 1], a_l[mi], b_all[jj][1], b_all[jj][3]);
                    }
            }
        }
    }

    const int g = lane >> 2, tg = lane & 3;
    const long long cbz = bz * sC;

    if (EPI == 3 || EPI == 4 || EPI == 5) {
        // stage tile fp32 in smem [row(m) * 129 + col(n)], transposed coalesced stores
        __syncthreads();
        float* Dsm = (float*)sm;
        #pragma unroll
        for (int mi = 0; mi < 2; mi++)
            #pragma unroll
            for (int j = 0; j < 8; j++)
                #pragma unroll
                for (int h = 0; h < 2; h++) {
                    const int row = wm + mi * 16 + g + h * 8;
                    const int col = wn + j * 8 + tg * 2;
                    Dsm[row * 129 + col]     = acc[mi][j][h * 2];
                    Dsm[row * 129 + col + 1] = acc[mi][j][h * 2 + 1];
                }
        __syncthreads();

        if (EPI == 3 || EPI == 5) {
            // out[n][h1*256 + o]; row = 128 fp16 = 256B = 16 lanes x 16B.
            const int h1 = n0 >> 11;
            const int xb = n0 & 2047;
            const int lane16 = lane & 15;
            const int sub = lane >> 4;                 // 2 rows per warp per pass
            #pragma unroll
            for (int p = 0; p < 8; p++) {
                const int n_loc = p * 16 + wid * 2 + sub;
                __align__(16) __half hbuf[8], lbuf[8];
                #pragma unroll
                for (int j = 0; j < 8; j++) {
                    if (EPI == 3) hsplit(Dsm[(lane16 * 8 + j) * 129 + n_loc], hbuf[j], lbuf[j]);
                    else          hbuf[j] = __float2half(Dsm[(lane16 * 8 + j) * 129 + n_loc]);
                }
                const long long ob = cbz + (long long)(xb + n_loc) * ldc
                                   + h1 * 256 + m0 + lane16 * 8;
                *(uint4*)(Ch + ob) = *(uint4*)hbuf;
                if (EPI == 3) *(uint4*)(Cl + ob) = *(uint4*)lbuf;
            }
        } else {
            // y3[h1*2048 + n0 + m][m0/2 + o2]; row = 64 fp16 = 128B = 8 lanes x 16B.
            const int lane8 = lane & 7;
            const int rsub = lane >> 3;                // 4 rows per warp per pass
            #pragma unroll
            for (int p = 0; p < 8; p++) {
                const int R = p * 32 + wid * 4 + rsub; // 0..255
                const int h1 = R >> 7;
                const int m_loc = R & 127;
                __align__(16) __half hbuf[8];
                #pragma unroll
                for (int j = 0; j < 8; j++)
                    hbuf[j] = __float2half(Dsm[(2 * (lane8 * 8 + j) + h1) * 129 + m_loc]);
                const long long ob = cbz + (long long)(h1 * 2048 + n0 + m_loc) * ldc
                                   + (m0 >> 1) + lane8 * 8;
                *(uint4*)(Ch + ob) = *(uint4*)hbuf;
            }
        }
        return;
    }

    // direct epilogues (0/1/2)
    #pragma unroll
    for (int mi = 0; mi < 2; mi++) {
        #pragma unroll
        for (int j = 0; j < 8; j++) {
            const int row = m0 + wm + mi * 16 + g;
            const int col = n0 + wn + j * 8 + tg * 2;
            #pragma unroll
            for (int h = 0; h < 2; h++) {
                const long long idx = cbz + (long long)(row + h * 8) * ldc + col;
                const float d0 = acc[mi][j][h * 2];
                const float d1 = acc[mi][j][h * 2 + 1];
                if (EPI == 0) {
                    *(float2*)(C + idx) = make_float2(d0, d1);
                } else if (EPI == 2) {
                    const float2 a = *(const float2*)(r1 + idx);
                    const float2 b = *(const float2*)(r2 + idx);
                    *(float2*)(C + idx) = make_float2(d0 + a.x + b.x, d1 + a.y + b.y);
                } else {
                    *(__half2*)(Ch + idx) =
                        __halves2half2(__float2half(d0), __float2half(d1));
                }
            }
        }
    }
}

// ---------------------------------------------------------------------------
// conversion kernels
// ---------------------------------------------------------------------------
__global__ void __launch_bounds__(256) split4_kernel(
    const float* __restrict__ s0, const float* __restrict__ s1,
    const float* __restrict__ s2, const float* __restrict__ s3,
    __half* __restrict__ h0, __half* __restrict__ l0,
    __half* __restrict__ h1, __half* __restrict__ l1,
    __half* __restrict__ h2, __half* __restrict__ l2,
    __half* __restrict__ h3, __half* __restrict__ l3)
{
    const int i = blockIdx.x * 256 + threadIdx.x;
    const int wsel = blockIdx.y;
    const float* s = (wsel == 0) ? s0 : (wsel == 1) ? s1 : (wsel == 2) ? s2 : s3;
    __half* hh = (wsel == 0) ? h0 : (wsel == 1) ? h1 : (wsel == 2) ? h2 : h3;
    __half* ll = (wsel == 0) ? l0 : (wsel == 1) ? l1 : (wsel == 2) ? l2 : l3;
    __half h, l;
    hsplit(s[i], h, l);
    hh[i] = h; ll[i] = l;
}

// (b, 512, 4096) -> (b, 4096, 512), fp16 hi only
__global__ void __launch_bounds__(256) tconv_kernel(const float* __restrict__ in,
                                                    __half* __restrict__ oh) {
    __shared__ float T[32][33];
    const int tx = threadIdx.x & 31, ty = threadIdx.x >> 5;
    const int x0 = blockIdx.x * 32, c0 = blockIdx.y * 32;
    const float* I = in + (size_t)blockIdx.z * CH * HW;
    #pragma unroll
    for (int r = 0; r < 4; r++)
        T[ty + r * 8][tx] = I[(size_t)(c0 + ty + r * 8) * HW + x0 + tx];
    __syncthreads();
    const size_t ob = (size_t)blockIdx.z * HW * CH;
    #pragma unroll
    for (int r = 0; r < 4; r++) {
        const size_t o = ob + (size_t)(x0 + ty + r * 8) * CH + c0 + tx;
        oh[o] = __float2half(T[tx][ty + r * 8]);
    }
}

// row softmax (rows of length 2048) -> fp16
__global__ void __launch_bounds__(256) softmax_h_kernel(const float* __restrict__ S,
                                                        __half* __restrict__ Sh) {
    const size_t row = blockIdx.x;
    const float* p = S + row * HW2;
    const int tid = threadIdx.x;

    float4 v0 = ((const float4*)p)[tid];
    float4 v1 = ((const float4*)p)[tid + 256];

    float mx = fmaxf(fmaxf(fmaxf(v0.x, v0.y), fmaxf(v0.z, v0.w)),
                     fmaxf(fmaxf(v1.x, v1.y), fmaxf(v1.z, v1.w)));
    __shared__ float red[8];
    #pragma unroll
    for (int o = 16; o > 0; o >>= 1) mx = fmaxf(mx, __shfl_xor_sync(0xffffffffu, mx, o));
    if ((tid & 31) == 0) red[tid >> 5] = mx;
    __syncthreads();
    mx = red[0];
    #pragma unroll
    for (int i = 1; i < 8; i++) mx = fmaxf(mx, red[i]);
    __syncthreads();

    v0.x = __expf(v0.x - mx); v0.y = __expf(v0.y - mx);
    v0.z = __expf(v0.z - mx); v0.w = __expf(v0.w - mx);
    v1.x = __expf(v1.x - mx); v1.y = __expf(v1.y - mx);
    v1.z = __expf(v1.z - mx); v1.w = __expf(v1.w - mx);

    float sum = v0.x + v0.y + v0.z + v0.w + v1.x + v1.y + v1.z + v1.w;
    #pragma unroll
    for (int o = 16; o > 0; o >>= 1) sum += __shfl_xor_sync(0xffffffffu, sum, o);
    if ((tid & 31) == 0) red[tid >> 5] = sum;
    __syncthreads();
    sum = red[0];
    #pragma unroll
    for (int i = 1; i < 8; i++) sum += red[i];

    const float inv = 1.0f / sum;
    __half2* ph = (__half2*)(Sh + row * HW2);
    ph[tid * 2 + 0] = __halves2half2(__float2half(v0.x * inv), __float2half(v0.y * inv));
    ph[tid * 2 + 1] = __halves2half2(__float2half(v0.z * inv), __float2half(v0.w * inv));
    ph[(tid + 256) * 2 + 0] = __halves2half2(__float2half(v1.x * inv), __float2half(v1.y * inv));
    ph[(tid + 256) * 2 + 1] = __halves2half2(__float2half(v1.z * inv), __float2half(v1.w * inv));
}

// ---------------------------------------------------------------------------
extern "C" void kernel_launch(void* const* d_in, const int* in_sizes, int n_in,
                              void* d_out, int out_size)
{
    const float* q    = (const float*)d_in[0];
    const float* k    = (const float*)d_in[1];
    const float* v    = (const float*)d_in[2];
    const float* Wphi = (const float*)d_in[3];
    const float* Wth  = (const float*)d_in[4];
    const float* Wg   = (const float*)d_in[5];
    const float* Wm   = (const float*)d_in[6];
    float* out = (float*)d_out;

    // dynamic smem: TERMS=2 -> 2x48KB stages (epilogue Dsm 66048 fits);
    //               TERMS=1 -> 2x32KB stages; EPI=4 needs 66048 for Dsm.
    constexpr int SMEM2  = 98304;
    constexpr int SMEM1  = 65536;
    constexpr int SMEM1E = 66560;
    cudaFuncSetAttribute(mma_gemm<3,2>, cudaFuncAttributeMaxDynamicSharedMemorySize, SMEM2);
    cudaFuncSetAttribute(mma_gemm<5,2>, cudaFuncAttributeMaxDynamicSharedMemorySize, SMEM2);
    cudaFuncSetAttribute(mma_gemm<0,2>, cudaFuncAttributeMaxDynamicSharedMemorySize, SMEM2);
    cudaFuncSetAttribute(mma_gemm<1,1>, cudaFuncAttributeMaxDynamicSharedMemorySize, SMEM1);
    cudaFuncSetAttribute(mma_gemm<4,1>, cudaFuncAttributeMaxDynamicSharedMemorySize, SMEM1E);
    cudaFuncSetAttribute(mma_gemm<2,1>, cudaFuncAttributeMaxDynamicSharedMemorySize, SMEM1);

    float* S;
    cudaGetSymbolAddress((void**)&S, g_S);
    __half *qTh, *kTh, *vTh;
    __half *Wph, *Wpl, *Wthh, *Wtl, *Wgh, *Wgl, *Wmh, *Wml;
    __half *gh, *pTh, *pTl, *tTh, *Sh, *y3h;
    cudaGetSymbolAddress((void**)&qTh, g_qTh);
    cudaGetSymbolAddress((void**)&kTh, g_kTh);
    cudaGetSymbolAddress((void**)&vTh, g_vTh);
    cudaGetSymbolAddress((void**)&Wph, g_Wph); cudaGetSymbolAddress((void**)&Wpl, g_Wpl);
    cudaGetSymbolAddress((void**)&Wthh, g_Wth); cudaGetSymbolAddress((void**)&Wtl, g_Wtl);
    cudaGetSymbolAddress((void**)&Wgh, g_Wgh); cudaGetSymbolAddress((void**)&Wgl, g_Wgl);
    cudaGetSymbolAddress((void**)&Wmh, g_Wmh); cudaGetSymbolAddress((void**)&Wml, g_Wml);
    cudaGetSymbolAddress((void**)&gh, g_gh);
    cudaGetSymbolAddress((void**)&pTh, g_pTh); cudaGetSymbolAddress((void**)&pTl, g_pTl);
    cudaGetSymbolAddress((void**)&tTh, g_tTh);
    cudaGetSymbolAddress((void**)&Sh, g_Sh);
    cudaGetSymbolAddress((void**)&y3h, g_y3h);

    const dim3 blk(256);
    const long long sX  = (long long)CH * HW;    // q/k/v/out batch stride
    const long long sT  = (long long)HW * CH;    // qT/kT/vT
    const long long sP  = (long long)CO * HW;    // g (==CH*HW2)
    const long long sPT = (long long)HW2 * CH;   // pT/tT
    const long long sS  = (long long)HW2 * HW2;  // scores
    const long long sY3 = (long long)HW * CO;    // y3

    // 0) weight splits (one launch)
    split4_kernel<<<dim3(CO * CH / 256, 4), blk>>>(Wphi, Wth, Wg, Wm,
                                                   Wph, Wpl, Wthh, Wtl,
                                                   Wgh, Wgl, Wmh, Wml);

    // 1) q/k transposes -> fp16 hi
    tconv_kernel<<<dim3(HW / 32, CH / 32, NB), blk>>>(q, qTh);
    tconv_kernel<<<dim3(HW / 32, CH / 32, NB), blk>>>(k, kTh);

    // 2) phi/theta convs (2-term, transposed epilogues)
    mma_gemm<3,2><<<dim3(HW / 128, CO / 128, NB), blk, SMEM2>>>(Wph, Wpl, qTh, nullptr, pTh, pTl,
                                                                CH, CH, 0, sT, sPT, nullptr, nullptr);
    mma_gemm<5,2><<<dim3(HW / 128, CO / 128, NB), blk, SMEM2>>>(Wthh, Wtl, kTh, nullptr, tTh, nullptr,
                                                                CH, CH, 0, sT, sPT, nullptr, nullptr);

    // 3) scores (2-term): S[m,n] = sum_k' pT[m,k'] * tT[n,k']
    mma_gemm<0,2><<<dim3(HW2 / 128, HW2 / 128, NB), blk, SMEM2>>>(pTh, pTl, tTh, S, nullptr, nullptr,
                                                                  CH, HW2, sPT, sPT, sS, nullptr, nullptr);

    // 4) v transpose + g conv
    tconv_kernel<<<dim3(HW / 32, CH / 32, NB), blk>>>(v, vTh);
    mma_gemm<1,1><<<dim3(HW / 128, CO / 128, NB), blk, SMEM1>>>(Wgh, nullptr, vTh, nullptr, gh, nullptr,
                                                                CH, HW, 0, sT, sP, nullptr, nullptr);

    // 5) row softmax -> fp16
    softmax_h_kernel<<<NB * HW2, blk>>>(S, Sh);

    // 6) attn apply (1-term, EPI=4): writes y3h transposed directly
    mma_gemm<4,1><<<dim3(HW2 / 128, CH / 128, NB), blk, SMEM1E>>>(gh, nullptr, Sh, nullptr, y3h, nullptr,
                                                                  HW2, CO, sP, sS, sY3, nullptr, nullptr);

    // 7) mask conv (1-term) + residual: out = Wm @ y3 + q + v
    mma_gemm<2,1><<<dim3(HW / 128, CH / 128, NB), blk, SMEM1>>>(Wmh, nullptr, y3h, out, nullptr, nullptr,
                                                                CO, HW, 0, sY3, sX, q, v);
}

// round 13
// speedup vs baseline: 1.0806x; 1.0806x over previous
#include <cuda_runtime.h>
#include <cuda_fp16.h>
#include <cstdint>

constexpr int NB  = 8;
constexpr int CH  = 512;
constexpr int HW  = 4096;
constexpr int HW2 = 2048;
constexpr int CO  = 256;

// ---------------- device scratch ----------------
__device__ __align__(256) float g_S [(size_t)NB * HW2 * HW2];

// q,k,v transposed fp16 hi, contiguous: [q(8) | k(8) | v(8)] each (4096,512)
__device__ __align__(256) __half g_xTh[(size_t)3 * NB * HW * CH];
__device__ __align__(256) __half g_Wph[CO * CH], g_Wpl[CO * CH];
__device__ __align__(256) __half g_Wth[CO * CH], g_Wtl[CO * CH];
__device__ __align__(256) __half g_Wgh[CO * CH], g_Wgl[CO * CH];
__device__ __align__(256) __half g_Wmh[CH * CO], g_Wml[CH * CO];
__device__ __align__(256) __half g_gh [(size_t)NB * CH * HW2];
// pT then tT contiguous: [pT(8) | tT(8)] each (2048,512)
__device__ __align__(256) __half g_ptTh[(size_t)2 * NB * HW2 * CH];
__device__ __align__(256) __half g_pTl [(size_t)NB * HW2 * CH];
__device__ __align__(256) __half g_Sh [(size_t)NB * HW2 * HW2];
__device__ __align__(256) __half g_y3h[(size_t)NB * HW * CO];

// ---------------- helpers ----------------
__device__ __forceinline__ uint32_t s2u(const void* p) {
    uint32_t a;
    asm("{ .reg .u64 t; cvta.to.shared.u64 t, %1; cvt.u32.u64 %0, t; }" : "=r"(a) : "l"(p));
    return a;
}
__device__ __forceinline__ void hsplit(float v, __half& h, __half& l) {
    h = __float2half(v);
    l = __float2half(v - __half2float(h));
}
__device__ __forceinline__ void ldsm4(uint32_t* r, uint32_t addr) {
    asm volatile("ldmatrix.sync.aligned.m8n8.x4.shared.b16 {%0,%1,%2,%3}, [%4];"
                 : "=r"(r[0]), "=r"(r[1]), "=r"(r[2]), "=r"(r[3]) : "r"(addr));
}
__device__ __forceinline__ void mma16816(float* d, const uint32_t* a, uint32_t b0, uint32_t b1) {
    asm volatile("mma.sync.aligned.m16n8k16.row.col.f32.f16.f16.f32 "
                 "{%0,%1,%2,%3}, {%4,%5,%6,%7}, {%8,%9}, {%0,%1,%2,%3};"
                 : "+f"(d[0]), "+f"(d[1]), "+f"(d[2]), "+f"(d[3])
                 : "r"(a[0]), "r"(a[1]), "r"(a[2]), "r"(a[3]), "r"(b0), "r"(b1));
}
__device__ __forceinline__ void cpasync16(uint32_t s, const void* g) {
    asm volatile("cp.async.cg.shared.global [%0], [%1], 16;" :: "r"(s), "l"(g));
}
#define CP_COMMIT() asm volatile("cp.async.commit_group;" ::: "memory")
#define CP_WAIT1()  asm volatile("cp.async.wait_group 1;" ::: "memory")
#define CP_WAIT0()  asm volatile("cp.async.wait_group 0;" ::: "memory")

// smem per stage (32 KB stride): Ah @0, Al @8192 (TERMS==2 only), Bh @16384.
// Row = 64 B (32 fp16), chunk = 16 B, swizzle: chunk ^= (row>>1)&3
template <int TERMS>
__device__ __forceinline__ void load_stage(uint32_t sbase,
    const __half* pAh, const __half* pAl, const __half* pBh,
    int Ktot, int kofs, int tid)
{
    const int row = tid >> 1;
    const int c0 = (tid & 1) * 2;
    const long long gofs = (long long)row * Ktot + kofs;
    #pragma unroll
    for (int s = 0; s < 2; s++) {
        const int c = c0 + s;
        const uint32_t soff = row * 64 + ((c ^ ((row >> 1) & 3)) << 4);
        cpasync16(sbase +         soff, pAh + gofs + c * 8);
        if (TERMS == 2)
            cpasync16(sbase + 8192 + soff, pAl + gofs + c * 8);
        cpasync16(sbase + 16384 + soff, pBh + gofs + c * 8);
    }
}

// ---------------------------------------------------------------------------
// Split-fp16 tensor-core GEMM (mma.sync), BK=32, 3-stage cp.async pipeline.
// D(128x128 fp32 tile) = (Ah[+Al])(MxK) @ Bh^T(NxK), fp16 K-major.
// TERMS: 2 = hh + lh; 1 = hh only.
// PAIR: 1 = grid.z covers TWO problems (sel = bz>>3); A/W switched by sel,
//       B/C offsets fall out of bz*stride (operand buffers are contiguous);
//       lo-plane written only for sel==0.
// EPI: 0 fp32 store | 1 row-major hi | 2 fp32+r1+r2 | 3 transposed hi+lo (pT)
//      4 transposed hi parity-grouped (y3)
// ---------------------------------------------------------------------------
template <int EPI, int TERMS, int PAIR>
__global__ void __launch_bounds__(256, 2) mma_gemm(
    const __half* __restrict__ Ah, const __half* __restrict__ Al,
    const __half* __restrict__ Bh,
    float* __restrict__ C, __half* __restrict__ Ch, __half* __restrict__ Cl,
    int Ktot, int ldc,
    long long sA, long long sB, long long sC,
    const float* __restrict__ r1, const float* __restrict__ r2)
{
    extern __shared__ __align__(1024) char sm[];
    const int tid = threadIdx.x;
    const int wid = tid >> 5, lane = tid & 31;
    const uint32_t sb = s2u(sm);

    const int m0 = blockIdx.y * 128;
    const int n0 = blockIdx.x * 128;
    const long long bz = blockIdx.z;
    const int sel = PAIR ? (int)(bz >> 3) : 0;

    const __half* pAh = Ah + bz * sA + (long long)sel * CO * CH + (long long)m0 * Ktot;
    const __half* pAl = (TERMS == 2)
        ? (Al + bz * sA + (long long)sel * CO * CH + (long long)m0 * Ktot) : nullptr;
    const __half* pBh = Bh + bz * sB + (long long)n0 * Ktot;

    const int wm = (wid >> 1) * 32;
    const int wn = (wid & 1) * 64;

    float acc[2][8][4];
    #pragma unroll
    for (int i = 0; i < 2; i++)
        #pragma unroll
        for (int j = 0; j < 8; j++)
            #pragma unroll
            for (int t = 0; t < 4; t++) acc[i][j][t] = 0.0f;

    const int nch = Ktot >> 5;
    load_stage<TERMS>(sb, pAh, pAl, pBh, Ktot, 0, tid);
    CP_COMMIT();
    load_stage<TERMS>(sb + 32768, pAh, pAl, pBh, Ktot, 32, tid);
    CP_COMMIT();

    uint32_t stage = 0;
    uint32_t nstage = 2;
    for (int ic = 0; ic < nch; ic++) {
        CP_WAIT1();
        __syncthreads();
        if (ic + 2 < nch) {
            load_stage<TERMS>(sb + nstage * 32768, pAh, pAl, pBh,
                              Ktot, (ic + 2) << 5, tid);
        }
        CP_COMMIT();
        nstage = (nstage == 2) ? 0 : nstage + 1;

        const uint32_t st = sb + stage * 32768;
        stage = (stage == 2) ? 0 : stage + 1;
        #pragma unroll
        for (int kk = 0; kk < 32; kk += 16) {
            const int kc = (kk >> 3) + (lane >> 4);
            uint32_t a_h[2][4], a_l[2][4], b_all[4][4];
            #pragma unroll
            for (int mi = 0; mi < 2; mi++) {
                const int row = wm + mi * 16 + (lane & 15);
                const uint32_t ad = st + row * 64 + ((kc ^ ((row >> 1) & 3)) << 4);
                ldsm4(a_h[mi], ad);
                if (TERMS == 2) ldsm4(a_l[mi], ad + 8192);
            }
            #pragma unroll
            for (int jj = 0; jj < 4; jj++) {
                const int row = wn + jj * 16 + (lane & 15);
                const uint32_t bd = st + 16384 + row * 64 + ((kc ^ ((row >> 1) & 3)) << 4);
                ldsm4(b_all[jj], bd);
            }
            // hi pass: 16 independent MMAs
            #pragma unroll
            for (int jj = 0; jj < 4; jj++)
                #pragma unroll
                for (int mi = 0; mi < 2; mi++) {
                    mma16816(acc[mi][jj * 2],     a_h[mi], b_all[jj][0], b_all[jj][2]);
                    mma16816(acc[mi][jj * 2 + 1], a_h[mi], b_all[jj][1], b_all[jj][3]);
                }
            // lo pass
            if (TERMS == 2) {
                #pragma unroll
                for (int jj = 0; jj < 4; jj++)
                    #pragma unroll
                    for (int mi = 0; mi < 2; mi++) {
                        mma16816(acc[mi][jj * 2],     a_l[mi], b_all[jj][0], b_all[jj][2]);
                        mma16816(acc[mi][jj * 2 + 1], a_l[mi], b_all[jj][1], b_all[jj][3]);
                    }
            }
        }
    }

    const int g = lane >> 2, tg = lane & 3;
    const long long cbz = bz * sC;

    if (EPI == 3 || EPI == 4) {
        // stage tile fp32 in smem [row(m) * 129 + col(n)], transposed coalesced stores
        CP_WAIT0();
        __syncthreads();
        float* Dsm = (float*)sm;
        #pragma unroll
        for (int mi = 0; mi < 2; mi++)
            #pragma unroll
            for (int j = 0; j < 8; j++)
                #pragma unroll
                for (int h = 0; h < 2; h++) {
                    const int row = wm + mi * 16 + g + h * 8;
                    const int col = wn + j * 8 + tg * 2;
                    Dsm[row * 129 + col]     = acc[mi][j][h * 2];
                    Dsm[row * 129 + col + 1] = acc[mi][j][h * 2 + 1];
                }
        __syncthreads();

        if (EPI == 3) {
            // out[n][h1*256 + o]; row = 128 fp16 = 256B = 16 lanes x 16B.
            const bool wlo = (!PAIR) || (sel == 0);
            const int h1 = n0 >> 11;
            const int xb = n0 & 2047;
            const int lane16 = lane & 15;
            const int sub = lane >> 4;                 // 2 rows per warp per pass
            #pragma unroll
            for (int p = 0; p < 8; p++) {
                const int n_loc = p * 16 + wid * 2 + sub;
                __align__(16) __half hbuf[8], lbuf[8];
                #pragma unroll
                for (int j = 0; j < 8; j++)
                    hsplit(Dsm[(lane16 * 8 + j) * 129 + n_loc], hbuf[j], lbuf[j]);
                const long long ob = cbz + (long long)(xb + n_loc) * ldc
                                   + h1 * 256 + m0 + lane16 * 8;
                *(uint4*)(Ch + ob) = *(uint4*)hbuf;
                if (wlo) *(uint4*)(Cl + ob) = *(uint4*)lbuf;
            }
        } else {
            // y3[h1*2048 + n0 + m][m0/2 + o2]; row = 64 fp16 = 128B = 8 lanes x 16B.
            const int lane8 = lane & 7;
            const int rsub = lane >> 3;                // 4 rows per warp per pass
            #pragma unroll
            for (int p = 0; p < 8; p++) {
                const int R = p * 32 + wid * 4 + rsub; // 0..255
                const int h1 = R >> 7;
                const int m_loc = R & 127;
                __align__(16) __half hbuf[8];
                #pragma unroll
                for (int j = 0; j < 8; j++)
                    hbuf[j] = __float2half(Dsm[(2 * (lane8 * 8 + j) + h1) * 129 + m_loc]);
                const long long ob = cbz + (long long)(h1 * 2048 + n0 + m_loc) * ldc
                                   + (m0 >> 1) + lane8 * 8;
                *(uint4*)(Ch + ob) = *(uint4*)hbuf;
            }
        }
        return;
    }

    // direct epilogues (0/1/2)
    #pragma unroll
    for (int mi = 0; mi < 2; mi++) {
        #pragma unroll
        for (int j = 0; j < 8; j++) {
            const int row = m0 + wm + mi * 16 + g;
            const int col = n0 + wn + j * 8 + tg * 2;
            #pragma unroll
            for (int h = 0; h < 2; h++) {
                const long long idx = cbz + (long long)(row + h * 8) * ldc + col;
                const float d0 = acc[mi][j][h * 2];
                const float d1 = acc[mi][j][h * 2 + 1];
                if (EPI == 0) {
                    *(float2*)(C + idx) = make_float2(d0, d1);
                } else if (EPI == 2) {
                    const float2 a = *(const float2*)(r1 + idx);
                    const float2 b = *(const float2*)(r2 + idx);
                    *(float2*)(C + idx) = make_float2(d0 + a.x + b.x, d1 + a.y + b.y);
                } else {
                    *(__half2*)(Ch + idx) =
                        __halves2half2(__float2half(d0), __float2half(d1));
                }
            }
        }
    }
}

// ---------------------------------------------------------------------------
// conversion kernels
// ---------------------------------------------------------------------------
__global__ void __launch_bounds__(256) split4_kernel(
    const float* __restrict__ s0, const float* __restrict__ s1,
    const float* __restrict__ s2, const float* __restrict__ s3,
    __half* __restrict__ h0, __half* __restrict__ l0,
    __half* __restrict__ h1, __half* __restrict__ l1,
    __half* __restrict__ h2, __half* __restrict__ l2,
    __half* __restrict__ h3, __half* __restrict__ l3)
{
    const int i = blockIdx.x * 256 + threadIdx.x;
    const int wsel = blockIdx.y;
    const float* s = (wsel == 0) ? s0 : (wsel == 1) ? s1 : (wsel == 2) ? s2 : s3;
    __half* hh = (wsel == 0) ? h0 : (wsel == 1) ? h1 : (wsel == 2) ? h2 : h3;
    __half* ll = (wsel == 0) ? l0 : (wsel == 1) ? l1 : (wsel == 2) ? l2 : l3;
    __half h, l;
    hsplit(s[i], h, l);
    hh[i] = h; ll[i] = l;
}

// all of q,k,v: (b,512,4096) -> (b,4096,512) fp16 hi, z = 0..23 selects tensor+batch
__global__ void __launch_bounds__(256) tconv3_kernel(const float* __restrict__ q,
                                                     const float* __restrict__ k,
                                                     const float* __restrict__ v,
                                                     __half* __restrict__ oh) {
    __shared__ float T[32][33];
    const int z = blockIdx.z;
    const int b = z & 7;
    const float* src = (z < NB) ? q : (z < 2 * NB) ? k : v;
    const float* I = src + (size_t)b * CH * HW;
    const int tx = threadIdx.x & 31, ty = threadIdx.x >> 5;
    const int x0 = blockIdx.x * 32, c0 = blockIdx.y * 32;
    #pragma unroll
    for (int r = 0; r < 4; r++)
        T[ty + r * 8][tx] = I[(size_t)(c0 + ty + r * 8) * HW + x0 + tx];
    __syncthreads();
    const size_t ob = (size_t)z * HW * CH;
    #pragma unroll
    for (int r = 0; r < 4; r++) {
        const size_t o = ob + (size_t)(x0 + ty + r * 8) * CH + c0 + tx;
        oh[o] = __float2half(T[tx][ty + r * 8]);
    }
}

// row softmax (rows of length 2048) -> fp16
__global__ void __launch_bounds__(256) softmax_h_kernel(const float* __restrict__ S,
                                                        __half* __restrict__ Sh) {
    const size_t row = blockIdx.x;
    const float* p = S + row * HW2;
    const int tid = threadIdx.x;

    float4 v0 = ((const float4*)p)[tid];
    float4 v1 = ((const float4*)p)[tid + 256];

    float mx = fmaxf(fmaxf(fmaxf(v0.x, v0.y), fmaxf(v0.z, v0.w)),
                     fmaxf(fmaxf(v1.x, v1.y), fmaxf(v1.z, v1.w)));
    __shared__ float red[8];
    #pragma unroll
    for (int o = 16; o > 0; o >>= 1) mx = fmaxf(mx, __shfl_xor_sync(0xffffffffu, mx, o));
    if ((tid & 31) == 0) red[tid >> 5] = mx;
    __syncthreads();
    mx = red[0];
    #pragma unroll
    for (int i = 1; i < 8; i++) mx = fmaxf(mx, red[i]);
    __syncthreads();

    v0.x = __expf(v0.x - mx); v0.y = __expf(v0.y - mx);
    v0.z = __expf(v0.z - mx); v0.w = __expf(v0.w - mx);
    v1.x = __expf(v1.x - mx); v1.y = __expf(v1.y - mx);
    v1.z = __expf(v1.z - mx); v1.w = __expf(v1.w - mx);

    float sum = v0.x + v0.y + v0.z + v0.w + v1.x + v1.y + v1.z + v1.w;
    #pragma unroll
    for (int o = 16; o > 0; o >>= 1) sum += __shfl_xor_sync(0xffffffffu, sum, o);
    if ((tid & 31) == 0) red[tid >> 5] = sum;
    __syncthreads();
    sum = red[0];
    #pragma unroll
    for (int i = 1; i < 8; i++) sum += red[i];

    const float inv = 1.0f / sum;
    __half2* ph = (__half2*)(Sh + row * HW2);
    ph[tid * 2 + 0] = __halves2half2(__float2half(v0.x * inv), __float2half(v0.y * inv));
    ph[tid * 2 + 1] = __halves2half2(__float2half(v0.z * inv), __float2half(v0.w * inv));
    ph[(tid + 256) * 2 + 0] = __halves2half2(__float2half(v1.x * inv), __float2half(v1.y * inv));
    ph[(tid + 256) * 2 + 1] = __halves2half2(__float2half(v1.z * inv), __float2half(v1.w * inv));
}

// ---------------------------------------------------------------------------
extern "C" void kernel_launch(void* const* d_in, const int* in_sizes, int n_in,
                              void* d_out, int out_size)
{
    const float* q    = (const float*)d_in[0];
    const float* k    = (const float*)d_in[1];
    const float* v    = (const float*)d_in[2];
    const float* Wphi = (const float*)d_in[3];
    const float* Wth  = (const float*)d_in[4];
    const float* Wg   = (const float*)d_in[5];
    const float* Wm   = (const float*)d_in[6];
    float* out = (float*)d_out;

    constexpr int SMEM = 98304;   // 3 stages x 32 KB stride (epilogue reuses)
    cudaFuncSetAttribute(mma_gemm<3,2,1>, cudaFuncAttributeMaxDynamicSharedMemorySize, SMEM);
    cudaFuncSetAttribute(mma_gemm<1,1,0>, cudaFuncAttributeMaxDynamicSharedMemorySize, SMEM);
    cudaFuncSetAttribute(mma_gemm<0,2,0>, cudaFuncAttributeMaxDynamicSharedMemorySize, SMEM);
    cudaFuncSetAttribute(mma_gemm<4,1,0>, cudaFuncAttributeMaxDynamicSharedMemorySize, SMEM);
    cudaFuncSetAttribute(mma_gemm<2,1,0>, cudaFuncAttributeMaxDynamicSharedMemorySize, SMEM);

    float* S;
    cudaGetSymbolAddress((void**)&S, g_S);
    __half *xTh;
    __half *Wph, *Wpl, *Wgh, *Wgl, *Wmh, *Wml;   // (Wth/Wtl live at offset CO*CH after Wph/Wpl)
    __half *dummy_h, *dummy_l;
    __half *gh, *ptTh, *pTl, *Sh, *y3h;
    cudaGetSymbolAddress((void**)&xTh, g_xTh);
    cudaGetSymbolAddress((void**)&Wph, g_Wph); cudaGetSymbolAddress((void**)&Wpl, g_Wpl);
    cudaGetSymbolAddress((void**)&dummy_h, g_Wth); cudaGetSymbolAddress((void**)&dummy_l, g_Wtl);
    cudaGetSymbolAddress((void**)&Wgh, g_Wgh); cudaGetSymbolAddress((void**)&Wgl, g_Wgl);
    cudaGetSymbolAddress((void**)&Wmh, g_Wmh); cudaGetSymbolAddress((void**)&Wml, g_Wml);
    cudaGetSymbolAddress((void**)&gh, g_gh);
    cudaGetSymbolAddress((void**)&ptTh, g_ptTh);
    cudaGetSymbolAddress((void**)&pTl, g_pTl);
    cudaGetSymbolAddress((void**)&Sh, g_Sh);
    cudaGetSymbolAddress((void**)&y3h, g_y3h);

    const dim3 blk(256);
    const long long sX  = (long long)CH * HW;    // q/k/v/out batch stride
    const long long sT  = (long long)HW * CH;    // xT per-z stride
    const long long sP  = (long long)CO * HW;    // g
    const long long sPT = (long long)HW2 * CH;   // pT/tT per-z stride
    const long long sS  = (long long)HW2 * HW2;  // scores
    const long long sY3 = (long long)HW * CO;    // y3

    __half* vTh = xTh + (size_t)2 * NB * sT;
    __half* tTh = ptTh + (size_t)NB * sPT;

    // NOTE: mma_gemm<3,2,1> PAIR mode requires (Wph,Wpl) and (Wth,Wtl) to sit at
    // +CO*CH from each other; the __device__ arrays are declared adjacently and
    // the kernel indexes A + sel*CO*CH. g_Wth must immediately follow g_Wph in
    // memory — guaranteed by passing Wth's own address when sel==1 is impossible,
    // so instead we pass base pointers and rely on sel offset. To be safe we copy
    // theta weights into the slot right after phi: use split4 to write them there.
    // split4 targets: h0/l0 = Wph/Wpl (sel 0), h1/l1 = Wph+CO*CH / Wpl+CO*CH (sel 1).
    __half* Wth_h = Wph + CO * CH;   // theta hi placed contiguously after phi hi
    __half* Wtl_l = Wpl + CO * CH;   // theta lo placed contiguously after phi lo
    (void)dummy_h; (void)dummy_l;

    // 0) weight splits (one launch). NOTE g_Wph/g_Wpl are sized CO*CH but we index
    // +CO*CH for theta — so alias into g_Wth/g_Wtl? Not guaranteed adjacent.
    // Instead: reuse g_Wth buffer via explicit pointer = Wth_h computed above is
    // WRONG unless adjacency holds. Use the safe route: write theta into
    // g_ptTh tail scratch (unused before conv): theta weights at pTl + huge? Keep
    // it simple and safe: place phi+theta weights in ONE buffer g_Sh head
    // (g_Sh is unused until softmax, conv pair finishes long before). 
    __half* Wpair_h = Sh;                         // [2*CO*CH] hi: phi | theta
    __half* Wpair_l = Sh + 2 * CO * CH;           // [2*CO*CH] lo: phi | theta
    split4_kernel<<<dim3(CO * CH / 256, 4), blk>>>(Wphi, Wth, Wg, Wm,
                                                   Wpair_h, Wpair_l,
                                                   Wpair_h + CO * CH, Wpair_l + CO * CH,
                                                   Wgh, Wgl, Wmh, Wml);

    // 1) q/k/v transposes -> fp16 hi (one launch, z = 0..23)
    tconv3_kernel<<<dim3(HW / 32, CH / 32, 3 * NB), blk>>>(q, k, v, xTh);

    // 2) phi+theta convs in ONE launch (PAIR=1, z = 0..15). B walks q then k;
    //    C walks pT then tT; lo written only for phi (sel==0).
    mma_gemm<3,2,1><<<dim3(HW / 128, CO / 128, 2 * NB), blk, SMEM>>>(
        Wpair_h, Wpair_l, xTh, nullptr, ptTh, pTl,
        CH, CH, 0, sT, sPT, nullptr, nullptr);

    // 3) g conv (1-term, row-major hi)
    mma_gemm<1,1,0><<<dim3(HW / 128, CO / 128, NB), blk, SMEM>>>(
        Wgh, nullptr, vTh, nullptr, gh, nullptr,
        CH, HW, 0, sT, sP, nullptr, nullptr);

    // 4) scores (2-term): S[m,n] = sum_k' pT[m,k'] * tT[n,k']
    mma_gemm<0,2,0><<<dim3(HW2 / 128, HW2 / 128, NB), blk, SMEM>>>(
        ptTh, pTl, tTh, S, nullptr, nullptr,
        CH, HW2, sPT, sPT, sS, nullptr, nullptr);

    // 5) row softmax -> fp16 (overwrites g_Sh head where pair-weights lived; the
    //    conv pair consumed them already)
    softmax_h_kernel<<<NB * HW2, blk>>>(S, Sh);

    // 6) attn apply (1-term, EPI=4): writes y3h transposed directly
    mma_gemm<4,1,0><<<dim3(HW2 / 128, CH / 128, NB), blk, SMEM>>>(
        gh, nullptr, Sh, nullptr, y3h, nullptr,
        HW2, CO, sP, sS, sY3, nullptr, nullptr);

    // 7) mask conv (1-term) + residual: out = Wm @ y3 + q + v
    mma_gemm<2,1,0><<<dim3(HW / 128, CH / 128, NB), blk, SMEM>>>(
        Wmh, nullptr, y3h, out, nullptr, nullptr,
        CO, HW, 0, sY3, sX, q, v);
}

// round 14
// speedup vs baseline: 1.0862x; 1.0052x over previous
#include <cuda_runtime.h>
#include <cuda_fp16.h>
#include <cstdint>

constexpr int NB  = 8;
constexpr int CH  = 512;
constexpr int HW  = 4096;
constexpr int HW2 = 2048;
constexpr int CO  = 256;

// ---------------- device scratch ----------------
__device__ __align__(256) float g_S [(size_t)NB * HW2 * HW2];

// q,k,v transposed fp16 hi, contiguous: [q(8) | k(8) | v(8)] each (4096,512)
__device__ __align__(256) __half g_xTh[(size_t)3 * NB * HW * CH];
__device__ __align__(256) __half g_Wmh[CH * CO], g_Wml[CH * CO];
__device__ __align__(256) __half g_gh [(size_t)NB * CH * HW2];
// pT then tT contiguous: [pT(8) | tT(8)] each (2048,512)
__device__ __align__(256) __half g_ptTh[(size_t)2 * NB * HW2 * CH];
__device__ __align__(256) __half g_pTl [(size_t)NB * HW2 * CH];
__device__ __align__(256) __half g_Sh [(size_t)NB * HW2 * HW2];   // head doubles as W3 scratch pre-softmax
__device__ __align__(256) __half g_y3h[(size_t)NB * HW * CO];

// ---------------- helpers ----------------
__device__ __forceinline__ uint32_t s2u(const void* p) {
    uint32_t a;
    asm("{ .reg .u64 t; cvta.to.shared.u64 t, %1; cvt.u32.u64 %0, t; }" : "=r"(a) : "l"(p));
    return a;
}
__device__ __forceinline__ void hsplit(float v, __half& h, __half& l) {
    h = __float2half(v);
    l = __float2half(v - __half2float(h));
}
__device__ __forceinline__ void ldsm4(uint32_t* r, uint32_t addr) {
    asm volatile("ldmatrix.sync.aligned.m8n8.x4.shared.b16 {%0,%1,%2,%3}, [%4];"
                 : "=r"(r[0]), "=r"(r[1]), "=r"(r[2]), "=r"(r[3]) : "r"(addr));
}
__device__ __forceinline__ void mma16816(float* d, const uint32_t* a, uint32_t b0, uint32_t b1) {
    asm volatile("mma.sync.aligned.m16n8k16.row.col.f32.f16.f16.f32 "
                 "{%0,%1,%2,%3}, {%4,%5,%6,%7}, {%8,%9}, {%0,%1,%2,%3};"
                 : "+f"(d[0]), "+f"(d[1]), "+f"(d[2]), "+f"(d[3])
                 : "r"(a[0]), "r"(a[1]), "r"(a[2]), "r"(a[3]), "r"(b0), "r"(b1));
}
__device__ __forceinline__ void cpasync16(uint32_t s, const void* g) {
    asm volatile("cp.async.cg.shared.global [%0], [%1], 16;" :: "r"(s), "l"(g));
}
#define CP_COMMIT() asm volatile("cp.async.commit_group;" ::: "memory")
#define CP_WAIT1()  asm volatile("cp.async.wait_group 1;" ::: "memory")
#define CP_WAIT0()  asm volatile("cp.async.wait_group 0;" ::: "memory")

// smem per stage (32 KB stride): Ah @0, Al @8192 (TERMS==2 only), Bh @16384.
// Row = 64 B (32 fp16), chunk = 16 B, swizzle: chunk ^= (row>>1)&3
template <int TERMS>
__device__ __forceinline__ void load_stage(uint32_t sbase,
    const __half* pAh, const __half* pAl, const __half* pBh,
    int Ktot, int kofs, int tid)
{
    const int row = tid >> 1;
    const int c0 = (tid & 1) * 2;
    const long long gofs = (long long)row * Ktot + kofs;
    #pragma unroll
    for (int s = 0; s < 2; s++) {
        const int c = c0 + s;
        const uint32_t soff = row * 64 + ((c ^ ((row >> 1) & 3)) << 4);
        cpasync16(sbase +         soff, pAh + gofs + c * 8);
        if (TERMS == 2)
            cpasync16(sbase + 8192 + soff, pAl + gofs + c * 8);
        cpasync16(sbase + 16384 + soff, pBh + gofs + c * 8);
    }
}

// ---------------------------------------------------------------------------
// Split-fp16 tensor-core GEMM (mma.sync), BK=32, 3-stage cp.async pipeline.
// D(128x128 fp32 tile) = (Ah[+Al])(MxK) @ Bh^T(NxK), fp16 K-major.
// TERMS: 2 = hh + lh; 1 = hh only.
// EPI: 0 fp32 store | 2 fp32+r1+r2 | 4 transposed hi parity-grouped (y3)
//      6 TRIPLE conv: z = 0..23, sel = z>>3. A = W3 + sel*CO*CH.
//        sel<2: transposed hi(+lo if sel==0) store (pT/tT), lo-MMA pass on.
//        sel==2: hi-pass only; row-major hi store to G (g conv).
// ---------------------------------------------------------------------------
template <int EPI, int TERMS>
__global__ void __launch_bounds__(256, 2) mma_gemm(
    const __half* __restrict__ Ah, const __half* __restrict__ Al,
    const __half* __restrict__ Bh,
    float* __restrict__ C, __half* __restrict__ Ch, __half* __restrict__ Cl,
    __half* __restrict__ G,
    int Ktot, int ldc,
    long long sA, long long sB, long long sC,
    const float* __restrict__ r1, const float* __restrict__ r2)
{
    extern __shared__ __align__(1024) char sm[];
    const int tid = threadIdx.x;
    const int wid = tid >> 5, lane = tid & 31;
    const uint32_t sb = s2u(sm);

    const int m0 = blockIdx.y * 128;
    const int n0 = blockIdx.x * 128;
    const long long bz = blockIdx.z;
    const int sel = (EPI == 6) ? (int)(bz >> 3) : 0;

    const __half* pAh = Ah + bz * sA + (long long)sel * CO * CH + (long long)m0 * Ktot;
    const __half* pAl = (TERMS == 2)
        ? (Al + bz * sA + (long long)sel * CO * CH + (long long)m0 * Ktot) : nullptr;
    const __half* pBh = Bh + bz * sB + (long long)n0 * Ktot;

    const bool do_lo = (TERMS == 2) && (EPI != 6 || sel < 2);

    const int wm = (wid >> 1) * 32;
    const int wn = (wid & 1) * 64;

    float acc[2][8][4];
    #pragma unroll
    for (int i = 0; i < 2; i++)
        #pragma unroll
        for (int j = 0; j < 8; j++)
            #pragma unroll
            for (int t = 0; t < 4; t++) acc[i][j][t] = 0.0f;

    const int nch = Ktot >> 5;
    load_stage<TERMS>(sb, pAh, pAl, pBh, Ktot, 0, tid);
    CP_COMMIT();
    load_stage<TERMS>(sb + 32768, pAh, pAl, pBh, Ktot, 32, tid);
    CP_COMMIT();

    uint32_t stage = 0;
    uint32_t nstage = 2;
    for (int ic = 0; ic < nch; ic++) {
        CP_WAIT1();
        __syncthreads();
        if (ic + 2 < nch) {
            load_stage<TERMS>(sb + nstage * 32768, pAh, pAl, pBh,
                              Ktot, (ic + 2) << 5, tid);
        }
        CP_COMMIT();
        nstage = (nstage == 2) ? 0 : nstage + 1;

        const uint32_t st = sb + stage * 32768;
        stage = (stage == 2) ? 0 : stage + 1;
        #pragma unroll
        for (int kk = 0; kk < 32; kk += 16) {
            const int kc = (kk >> 3) + (lane >> 4);
            uint32_t a_h[2][4], a_l[2][4], b_all[4][4];
            #pragma unroll
            for (int mi = 0; mi < 2; mi++) {
                const int row = wm + mi * 16 + (lane & 15);
                const uint32_t ad = st + row * 64 + ((kc ^ ((row >> 1) & 3)) << 4);
                ldsm4(a_h[mi], ad);
                if (TERMS == 2) ldsm4(a_l[mi], ad + 8192);
            }
            #pragma unroll
            for (int jj = 0; jj < 4; jj++) {
                const int row = wn + jj * 16 + (lane & 15);
                const uint32_t bd = st + 16384 + row * 64 + ((kc ^ ((row >> 1) & 3)) << 4);
                ldsm4(b_all[jj], bd);
            }
            // hi pass: 16 independent MMAs
            #pragma unroll
            for (int jj = 0; jj < 4; jj++)
                #pragma unroll
                for (int mi = 0; mi < 2; mi++) {
                    mma16816(acc[mi][jj * 2],     a_h[mi], b_all[jj][0], b_all[jj][2]);
                    mma16816(acc[mi][jj * 2 + 1], a_h[mi], b_all[jj][1], b_all[jj][3]);
                }
            // lo pass (skipped for g-conv slice of the TRIPLE)
            if (do_lo) {
                #pragma unroll
                for (int jj = 0; jj < 4; jj++)
                    #pragma unroll
                    for (int mi = 0; mi < 2; mi++) {
                        mma16816(acc[mi][jj * 2],     a_l[mi], b_all[jj][0], b_all[jj][2]);
                        mma16816(acc[mi][jj * 2 + 1], a_l[mi], b_all[jj][1], b_all[jj][3]);
                    }
            }
        }
    }

    const int g = lane >> 2, tg = lane & 3;

    if (EPI == 6 && sel == 2) {
        // g conv: row-major hi store, ld = HW, batch stride = CO*HW
        const long long gbz = (bz - 16) * (long long)CO * HW;
        #pragma unroll
        for (int mi = 0; mi < 2; mi++)
            #pragma unroll
            for (int j = 0; j < 8; j++) {
                const int row = m0 + wm + mi * 16 + g;
                const int col = n0 + wn + j * 8 + tg * 2;
                #pragma unroll
                for (int h = 0; h < 2; h++) {
                    const long long idx = gbz + (long long)(row + h * 8) * HW + col;
                    *(__half2*)(G + idx) = __halves2half2(
                        __float2half(acc[mi][j][h * 2]), __float2half(acc[mi][j][h * 2 + 1]));
                }
            }
        return;
    }

    const long long cbz = bz * sC;

    if (EPI == 6 || EPI == 4) {
        // stage tile fp32 in smem [row(m) * 129 + col(n)], transposed coalesced stores
        CP_WAIT0();
        __syncthreads();
        float* Dsm = (float*)sm;
        #pragma unroll
        for (int mi = 0; mi < 2; mi++)
            #pragma unroll
            for (int j = 0; j < 8; j++)
                #pragma unroll
                for (int h = 0; h < 2; h++) {
                    const int row = wm + mi * 16 + g + h * 8;
                    const int col = wn + j * 8 + tg * 2;
                    Dsm[row * 129 + col]     = acc[mi][j][h * 2];
                    Dsm[row * 129 + col + 1] = acc[mi][j][h * 2 + 1];
                }
        __syncthreads();

        if (EPI == 6) {
            // pT/tT: out[n][h1*256 + o]; row = 128 fp16 = 256B = 16 lanes x 16B.
            const bool wlo = (sel == 0);
            const int h1 = n0 >> 11;
            const int xb = n0 & 2047;
            const int lane16 = lane & 15;
            const int sub = lane >> 4;                 // 2 rows per warp per pass
            #pragma unroll
            for (int p = 0; p < 8; p++) {
                const int n_loc = p * 16 + wid * 2 + sub;
                __align__(16) __half hbuf[8], lbuf[8];
                #pragma unroll
                for (int j = 0; j < 8; j++)
                    hsplit(Dsm[(lane16 * 8 + j) * 129 + n_loc], hbuf[j], lbuf[j]);
                const long long ob = cbz + (long long)(xb + n_loc) * ldc
                                   + h1 * 256 + m0 + lane16 * 8;
                *(uint4*)(Ch + ob) = *(uint4*)hbuf;
                if (wlo) *(uint4*)(Cl + ob) = *(uint4*)lbuf;
            }
        } else {
            // y3[h1*2048 + n0 + m][m0/2 + o2]; row = 64 fp16 = 128B = 8 lanes x 16B.
            const int lane8 = lane & 7;
            const int rsub = lane >> 3;                // 4 rows per warp per pass
            #pragma unroll
            for (int p = 0; p < 8; p++) {
                const int R = p * 32 + wid * 4 + rsub; // 0..255
                const int h1 = R >> 7;
                const int m_loc = R & 127;
                __align__(16) __half hbuf[8];
                #pragma unroll
                for (int j = 0; j < 8; j++)
                    hbuf[j] = __float2half(Dsm[(2 * (lane8 * 8 + j) + h1) * 129 + m_loc]);
                const long long ob = cbz + (long long)(h1 * 2048 + n0 + m_loc) * ldc
                                   + (m0 >> 1) + lane8 * 8;
                *(uint4*)(Ch + ob) = *(uint4*)hbuf;
            }
        }
        return;
    }

    // direct epilogues (0/2)
    #pragma unroll
    for (int mi = 0; mi < 2; mi++) {
        #pragma unroll
        for (int j = 0; j < 8; j++) {
            const int row = m0 + wm + mi * 16 + g;
            const int col = n0 + wn + j * 8 + tg * 2;
            #pragma unroll
            for (int h = 0; h < 2; h++) {
                const long long idx = cbz + (long long)(row + h * 8) * ldc + col;
                const float d0 = acc[mi][j][h * 2];
                const float d1 = acc[mi][j][h * 2 + 1];
                if (EPI == 0) {
                    *(float2*)(C + idx) = make_float2(d0, d1);
                } else {
                    const float2 a = *(const float2*)(r1 + idx);
                    const float2 b = *(const float2*)(r2 + idx);
                    *(float2*)(C + idx) = make_float2(d0 + a.x + b.x, d1 + a.y + b.y);
                }
            }
        }
    }
}

// ---------------------------------------------------------------------------
// conversion kernels
// ---------------------------------------------------------------------------
// 4 weight splits in one launch: phi/theta/g -> W3 (contiguous), mask -> Wm
__global__ void __launch_bounds__(256) split4_kernel(
    const float* __restrict__ s0, const float* __restrict__ s1,
    const float* __restrict__ s2, const float* __restrict__ s3,
    __half* __restrict__ w3h, __half* __restrict__ w3l,
    __half* __restrict__ wmh, __half* __restrict__ wml)
{
    const int i = blockIdx.x * 256 + threadIdx.x;
    const int wsel = blockIdx.y;
    const float* s = (wsel == 0) ? s0 : (wsel == 1) ? s1 : (wsel == 2) ? s2 : s3;
    __half* hh = (wsel == 3) ? wmh : (w3h + wsel * CO * CH);
    __half* ll = (wsel == 3) ? wml : (w3l + wsel * CO * CH);
    __half h, l;
    hsplit(s[i], h, l);
    hh[i] = h; ll[i] = l;
}

// q,k,v: (b,512,4096) -> (b,4096,512) fp16 hi, z = 0..23.
// Tile 64c x 32x; half2 stores (128B per warp transaction).
__global__ void __launch_bounds__(256) tconv3_kernel(const float* __restrict__ q,
                                                     const float* __restrict__ k,
                                                     const float* __restrict__ v,
                                                     __half* __restrict__ oh) {
    __shared__ float T[64][33];
    const int z = blockIdx.z;
    const int b = z & 7;
    const float* src = (z < NB) ? q : (z < 2 * NB) ? k : v;
    const float* I = src + (size_t)b * CH * HW;
    const int tx = threadIdx.x & 31, ty = threadIdx.x >> 5;
    const int x0 = blockIdx.x * 32, c0 = blockIdx.y * 64;
    #pragma unroll
    for (int r = 0; r < 8; r++) {
        const int cl = r * 8 + ty;
        T[cl][tx] = I[(size_t)(c0 + cl) * HW + x0 + tx];
    }
    __syncthreads();
    const size_t ob = (size_t)z * HW * CH;
    #pragma unroll
    for (int p = 0; p < 4; p++) {
        const int xl = p * 8 + ty;
        const __half2 val = __halves2half2(__float2half(T[2 * tx][xl]),
                                           __float2half(T[2 * tx + 1][xl]));
        *(__half2*)(oh + ob + (size_t)(x0 + xl) * CH + c0 + 2 * tx) = val;
    }
}

// row softmax (rows of length 2048) -> fp16
__global__ void __launch_bounds__(256) softmax_h_kernel(const float* __restrict__ S,
                                                        __half* __restrict__ Sh) {
    const size_t row = blockIdx.x;
    const float* p = S + row * HW2;
    const int tid = threadIdx.x;

    float4 v0 = ((const float4*)p)[tid];
    float4 v1 = ((const float4*)p)[tid + 256];

    float mx = fmaxf(fmaxf(fmaxf(v0.x, v0.y), fmaxf(v0.z, v0.w)),
                     fmaxf(fmaxf(v1.x, v1.y), fmaxf(v1.z, v1.w)));
    __shared__ float red[8];
    #pragma unroll
    for (int o = 16; o > 0; o >>= 1) mx = fmaxf(mx, __shfl_xor_sync(0xffffffffu, mx, o));
    if ((tid & 31) == 0) red[tid >> 5] = mx;
    __syncthreads();
    mx = red[0];
    #pragma unroll
    for (int i = 1; i < 8; i++) mx = fmaxf(mx, red[i]);
    __syncthreads();

    v0.x = __expf(v0.x - mx); v0.y = __expf(v0.y - mx);
    v0.z = __expf(v0.z - mx); v0.w = __expf(v0.w - mx);
    v1.x = __expf(v1.x - mx); v1.y = __expf(v1.y - mx);
    v1.z = __expf(v1.z - mx); v1.w = __expf(v1.w - mx);

    float sum = v0.x + v0.y + v0.z + v0.w + v1.x + v1.y + v1.z + v1.w;
    #pragma unroll
    for (int o = 16; o > 0; o >>= 1) sum += __shfl_xor_sync(0xffffffffu, sum, o);
    if ((tid & 31) == 0) red[tid >> 5] = sum;
    __syncthreads();
    sum = red[0];
    #pragma unroll
    for (int i = 1; i < 8; i++) sum += red[i];

    const float inv = 1.0f / sum;
    __half2* ph = (__half2*)(Sh + row * HW2);
    ph[tid * 2 + 0] = __halves2half2(__float2half(v0.x * inv), __float2half(v0.y * inv));
    ph[tid * 2 + 1] = __halves2half2(__float2half(v0.z * inv), __float2half(v0.w * inv));
    ph[(tid + 256) * 2 + 0] = __halves2half2(__float2half(v1.x * inv), __float2half(v1.y * inv));
    ph[(tid + 256) * 2 + 1] = __halves2half2(__float2half(v1.z * inv), __float2half(v1.w * inv));
}

// ---------------------------------------------------------------------------
extern "C" void kernel_launch(void* const* d_in, const int* in_sizes, int n_in,
                              void* d_out, int out_size)
{
    const float* q    = (const float*)d_in[0];
    const float* k    = (const float*)d_in[1];
    const float* v    = (const float*)d_in[2];
    const float* Wphi = (const float*)d_in[3];
    const float* Wth  = (const float*)d_in[4];
    const float* Wg   = (const float*)d_in[5];
    const float* Wm   = (const float*)d_in[6];
    float* out = (float*)d_out;

    constexpr int SMEM = 98304;   // 3 stages x 32 KB stride (epilogue reuses)
    cudaFuncSetAttribute(mma_gemm<6,2>, cudaFuncAttributeMaxDynamicSharedMemorySize, SMEM);
    cudaFuncSetAttribute(mma_gemm<0,2>, cudaFuncAttributeMaxDynamicSharedMemorySize, SMEM);
    cudaFuncSetAttribute(mma_gemm<4,1>, cudaFuncAttributeMaxDynamicSharedMemorySize, SMEM);
    cudaFuncSetAttribute(mma_gemm<2,1>, cudaFuncAttributeMaxDynamicSharedMemorySize, SMEM);

    float* S;
    cudaGetSymbolAddress((void**)&S, g_S);
    __half *xTh, *Wmh, *Wml, *gh, *ptTh, *pTl, *Sh, *y3h;
    cudaGetSymbolAddress((void**)&xTh, g_xTh);
    cudaGetSymbolAddress((void**)&Wmh, g_Wmh); cudaGetSymbolAddress((void**)&Wml, g_Wml);
    cudaGetSymbolAddress((void**)&gh, g_gh);
    cudaGetSymbolAddress((void**)&ptTh, g_ptTh);
    cudaGetSymbolAddress((void**)&pTl, g_pTl);
    cudaGetSymbolAddress((void**)&Sh, g_Sh);
    cudaGetSymbolAddress((void**)&y3h, g_y3h);

    const dim3 blk(256);
    const long long sX  = (long long)CH * HW;    // q/k/v/out batch stride
    const long long sT  = (long long)HW * CH;    // xT per-z stride
    const long long sP  = (long long)CO * HW;    // g
    const long long sPT = (long long)HW2 * CH;   // pT/tT per-z stride
    const long long sS  = (long long)HW2 * HW2;  // scores
    const long long sY3 = (long long)HW * CO;    // y3

    __half* tTh = ptTh + (size_t)NB * sPT;

    // phi|theta|g weights contiguous in g_Sh head (unused until softmax)
    __half* W3h = Sh;                   // [3*CO*CH]
    __half* W3l = Sh + 3 * CO * CH;     // [3*CO*CH]

    // 0) weight splits (one launch)
    split4_kernel<<<dim3(CO * CH / 256, 4), blk>>>(Wphi, Wth, Wg, Wm,
                                                   W3h, W3l, Wmh, Wml);

    // 1) q/k/v transposes -> fp16 hi (one launch, half2 stores)
    tconv3_kernel<<<dim3(HW / 32, CH / 64, 3 * NB), blk>>>(q, k, v, xTh);

    // 2) TRIPLE conv: phi(2t, hi+lo pT) | theta(2t, hi tT) | g(1t, row-major)
    mma_gemm<6,2><<<dim3(HW / 128, CO / 128, 3 * NB), blk, SMEM>>>(
        W3h, W3l, xTh, nullptr, ptTh, pTl, gh,
        CH, CH, 0, sT, sPT, nullptr, nullptr);

    // 3) scores (2-term): S[m,n] = sum_k' pT[m,k'] * tT[n,k']
    mma_gemm<0,2><<<dim3(HW2 / 128, HW2 / 128, NB), blk, SMEM>>>(
        ptTh, pTl, tTh, S, nullptr, nullptr, nullptr,
        CH, HW2, sPT, sPT, sS, nullptr, nullptr);

    // 4) row softmax -> fp16 (overwrites g_Sh head; weights already consumed)
    softmax_h_kernel<<<NB * HW2, blk>>>(S, Sh);

    // 5) attn apply (1-term, EPI=4): writes y3h transposed directly
    mma_gemm<4,1><<<dim3(HW2 / 128, CH / 128, NB), blk, SMEM>>>(
        gh, nullptr, Sh, nullptr, y3h, nullptr, nullptr,
        HW2, CO, sP, sS, sY3, nullptr, nullptr);

    // 6) mask conv (1-term) + residual: out = Wm @ y3 + q + v
    mma_gemm<2,1><<<dim3(HW / 128, CH / 128, NB), blk, SMEM>>>(
        Wmh, nullptr, y3h, out, nullptr, nullptr, nullptr,
        CO, HW, 0, sY3, sX, q, v);
}

// round 15
// speedup vs baseline: 1.2760x; 1.1747x over previous
#include <cuda_runtime.h>
#include <cuda_fp16.h>
#include <cstdint>

constexpr int NB  = 8;
constexpr int CH  = 512;
constexpr int HW  = 4096;
constexpr int HW2 = 2048;
constexpr int CO  = 256;

// ---------------- device scratch ----------------
__device__ __align__(256) float g_S [(size_t)NB * HW2 * HW2];

// q,k,v transposed fp16 hi, contiguous: [q(8) | k(8) | v(8)] each (4096,512)
__device__ __align__(256) __half g_xTh[(size_t)3 * NB * HW * CH];
__device__ __align__(256) __half g_Wmh[CH * CO], g_Wml[CH * CO];
__device__ __align__(256) __half g_gh [(size_t)NB * CH * HW2];
// pT then tT contiguous: [pT(8) | tT(8)] each (2048,512), hi only
__device__ __align__(256) __half g_ptTh[(size_t)2 * NB * HW2 * CH];
__device__ __align__(256) __half g_Sh [(size_t)NB * HW2 * HW2];   // head doubles as W3 scratch pre-softmax
__device__ __align__(256) __half g_y3h[(size_t)NB * HW * CO];

// ---------------- helpers ----------------
__device__ __forceinline__ uint32_t s2u(const void* p) {
    uint32_t a;
    asm("{ .reg .u64 t; cvta.to.shared.u64 t, %1; cvt.u32.u64 %0, t; }" : "=r"(a) : "l"(p));
    return a;
}
__device__ __forceinline__ void hsplit(float v, __half& h, __half& l) {
    h = __float2half(v);
    l = __float2half(v - __half2float(h));
}
__device__ __forceinline__ void ldsm4(uint32_t* r, uint32_t addr) {
    asm volatile("ldmatrix.sync.aligned.m8n8.x4.shared.b16 {%0,%1,%2,%3}, [%4];"
                 : "=r"(r[0]), "=r"(r[1]), "=r"(r[2]), "=r"(r[3]) : "r"(addr));
}
__device__ __forceinline__ void mma16816(float* d, const uint32_t* a, uint32_t b0, uint32_t b1) {
    asm volatile("mma.sync.aligned.m16n8k16.row.col.f32.f16.f16.f32 "
                 "{%0,%1,%2,%3}, {%4,%5,%6,%7}, {%8,%9}, {%0,%1,%2,%3};"
                 : "+f"(d[0]), "+f"(d[1]), "+f"(d[2]), "+f"(d[3])
                 : "r"(a[0]), "r"(a[1]), "r"(a[2]), "r"(a[3]), "r"(b0), "r"(b1));
}
__device__ __forceinline__ void cpasync16(uint32_t s, const void* g) {
    asm volatile("cp.async.cg.shared.global [%0], [%1], 16;" :: "r"(s), "l"(g));
}
#define CP_COMMIT() asm volatile("cp.async.commit_group;" ::: "memory")
#define CP_WAIT1()  asm volatile("cp.async.wait_group 1;" ::: "memory")
#define CP_WAIT0()  asm volatile("cp.async.wait_group 0;" ::: "memory")

// smem per stage (32 KB stride): Ah @0, Al @8192 (TERMS==2 only), Bh @16384.
// Row = 64 B (32 fp16), chunk = 16 B, swizzle: chunk ^= (row>>1)&3
template <int TERMS>
__device__ __forceinline__ void load_stage(uint32_t sbase,
    const __half* pAh, const __half* pAl, const __half* pBh,
    int Ktot, int kofs, int tid)
{
    const int row = tid >> 1;
    const int c0 = (tid & 1) * 2;
    const long long gofs = (long long)row * Ktot + kofs;
    #pragma unroll
    for (int s = 0; s < 2; s++) {
        const int c = c0 + s;
        const uint32_t soff = row * 64 + ((c ^ ((row >> 1) & 3)) << 4);
        cpasync16(sbase +         soff, pAh + gofs + c * 8);
        if (TERMS == 2)
            cpasync16(sbase + 8192 + soff, pAl + gofs + c * 8);
        cpasync16(sbase + 16384 + soff, pBh + gofs + c * 8);
    }
}

// ---------------------------------------------------------------------------
// Split-fp16 tensor-core GEMM (mma.sync), BK=32, 3-stage cp.async pipeline.
// D(128x128 fp32 tile) = (Ah[+Al])(MxK) @ Bh^T(NxK), fp16 K-major.
// TERMS: 2 = hh + lh; 1 = hh only.
// EPI: 0 fp32 store | 2 fp32+r1+r2 | 4 transposed hi parity-grouped (y3)
//      6 TRIPLE conv: z = 0..23, sel = z>>3. A = W3 + sel*CO*CH.
//        sel<2: 2-term MMA, transposed HI-ONLY store (pT/tT).
//        sel==2: hi-pass only; row-major hi store to G (g conv).
// ---------------------------------------------------------------------------
template <int EPI, int TERMS>
__global__ void __launch_bounds__(256, 2) mma_gemm(
    const __half* __restrict__ Ah, const __half* __restrict__ Al,
    const __half* __restrict__ Bh,
    float* __restrict__ C, __half* __restrict__ Ch,
    __half* __restrict__ G,
    int Ktot, int ldc,
    long long sA, long long sB, long long sC,
    const float* __restrict__ r1, const float* __restrict__ r2)
{
    extern __shared__ __align__(1024) char sm[];
    const int tid = threadIdx.x;
    const int wid = tid >> 5, lane = tid & 31;
    const uint32_t sb = s2u(sm);

    const int m0 = blockIdx.y * 128;
    const int n0 = blockIdx.x * 128;
    const long long bz = blockIdx.z;
    const int sel = (EPI == 6) ? (int)(bz >> 3) : 0;

    const __half* pAh = Ah + bz * sA + (long long)sel * CO * CH + (long long)m0 * Ktot;
    const __half* pAl = (TERMS == 2)
        ? (Al + bz * sA + (long long)sel * CO * CH + (long long)m0 * Ktot) : nullptr;
    const __half* pBh = Bh + bz * sB + (long long)n0 * Ktot;

    const bool do_lo = (TERMS == 2) && (EPI != 6 || sel < 2);

    const int wm = (wid >> 1) * 32;
    const int wn = (wid & 1) * 64;

    float acc[2][8][4];
    #pragma unroll
    for (int i = 0; i < 2; i++)
        #pragma unroll
        for (int j = 0; j < 8; j++)
            #pragma unroll
            for (int t = 0; t < 4; t++) acc[i][j][t] = 0.0f;

    const int nch = Ktot >> 5;
    load_stage<TERMS>(sb, pAh, pAl, pBh, Ktot, 0, tid);
    CP_COMMIT();
    load_stage<TERMS>(sb + 32768, pAh, pAl, pBh, Ktot, 32, tid);
    CP_COMMIT();

    uint32_t stage = 0;
    uint32_t nstage = 2;
    for (int ic = 0; ic < nch; ic++) {
        CP_WAIT1();
        __syncthreads();
        if (ic + 2 < nch) {
            load_stage<TERMS>(sb + nstage * 32768, pAh, pAl, pBh,
                              Ktot, (ic + 2) << 5, tid);
        }
        CP_COMMIT();
        nstage = (nstage == 2) ? 0 : nstage + 1;

        const uint32_t st = sb + stage * 32768;
        stage = (stage == 2) ? 0 : stage + 1;
        #pragma unroll
        for (int kk = 0; kk < 32; kk += 16) {
            const int kc = (kk >> 3) + (lane >> 4);
            uint32_t a_h[2][4], a_l[2][4], b_all[4][4];
            #pragma unroll
            for (int mi = 0; mi < 2; mi++) {
                const int row = wm + mi * 16 + (lane & 15);
                const uint32_t ad = st + row * 64 + ((kc ^ ((row >> 1) & 3)) << 4);
                ldsm4(a_h[mi], ad);
                if (TERMS == 2) ldsm4(a_l[mi], ad + 8192);
            }
            #pragma unroll
            for (int jj = 0; jj < 4; jj++) {
                const int row = wn + jj * 16 + (lane & 15);
                const uint32_t bd = st + 16384 + row * 64 + ((kc ^ ((row >> 1) & 3)) << 4);
                ldsm4(b_all[jj], bd);
            }
            // hi pass: 16 independent MMAs
            #pragma unroll
            for (int jj = 0; jj < 4; jj++)
                #pragma unroll
                for (int mi = 0; mi < 2; mi++) {
                    mma16816(acc[mi][jj * 2],     a_h[mi], b_all[jj][0], b_all[jj][2]);
                    mma16816(acc[mi][jj * 2 + 1], a_h[mi], b_all[jj][1], b_all[jj][3]);
                }
            // lo pass (conv phi/theta only)
            if (do_lo) {
                #pragma unroll
                for (int jj = 0; jj < 4; jj++)
                    #pragma unroll
                    for (int mi = 0; mi < 2; mi++) {
                        mma16816(acc[mi][jj * 2],     a_l[mi], b_all[jj][0], b_all[jj][2]);
                        mma16816(acc[mi][jj * 2 + 1], a_l[mi], b_all[jj][1], b_all[jj][3]);
                    }
            }
        }
    }

    const int g = lane >> 2, tg = lane & 3;

    if (EPI == 6 && sel == 2) {
        // g conv: row-major hi store, ld = HW, batch stride = CO*HW
        const long long gbz = (bz - 16) * (long long)CO * HW;
        #pragma unroll
        for (int mi = 0; mi < 2; mi++)
            #pragma unroll
            for (int j = 0; j < 8; j++) {
                const int row = m0 + wm + mi * 16 + g;
                const int col = n0 + wn + j * 8 + tg * 2;
                #pragma unroll
                for (int h = 0; h < 2; h++) {
                    const long long idx = gbz + (long long)(row + h * 8) * HW + col;
                    *(__half2*)(G + idx) = __halves2half2(
                        __float2half(acc[mi][j][h * 2]), __float2half(acc[mi][j][h * 2 + 1]));
                }
            }
        return;
    }

    const long long cbz = bz * sC;

    if (EPI == 6 || EPI == 4) {
        // stage tile fp32 in smem [row(m) * 129 + col(n)], transposed coalesced stores
        CP_WAIT0();
        __syncthreads();
        float* Dsm = (float*)sm;
        #pragma unroll
        for (int mi = 0; mi < 2; mi++)
            #pragma unroll
            for (int j = 0; j < 8; j++)
                #pragma unroll
                for (int h = 0; h < 2; h++) {
                    const int row = wm + mi * 16 + g + h * 8;
                    const int col = wn + j * 8 + tg * 2;
                    Dsm[row * 129 + col]     = acc[mi][j][h * 2];
                    Dsm[row * 129 + col + 1] = acc[mi][j][h * 2 + 1];
                }
        __syncthreads();

        if (EPI == 6) {
            // pT/tT: out[n][h1*256 + o] HI only; row = 128 fp16 = 256B = 16 lanes x 16B.
            const int h1 = n0 >> 11;
            const int xb = n0 & 2047;
            const int lane16 = lane & 15;
            const int sub = lane >> 4;                 // 2 rows per warp per pass
            #pragma unroll
            for (int p = 0; p < 8; p++) {
                const int n_loc = p * 16 + wid * 2 + sub;
                __align__(16) __half hbuf[8];
                #pragma unroll
                for (int j = 0; j < 8; j++)
                    hbuf[j] = __float2half(Dsm[(lane16 * 8 + j) * 129 + n_loc]);
                const long long ob = cbz + (long long)(xb + n_loc) * ldc
                                   + h1 * 256 + m0 + lane16 * 8;
                *(uint4*)(Ch + ob) = *(uint4*)hbuf;
            }
        } else {
            // y3[h1*2048 + n0 + m][m0/2 + o2]; row = 64 fp16 = 128B = 8 lanes x 16B.
            const int lane8 = lane & 7;
            const int rsub = lane >> 3;                // 4 rows per warp per pass
            #pragma unroll
            for (int p = 0; p < 8; p++) {
                const int R = p * 32 + wid * 4 + rsub; // 0..255
                const int h1 = R >> 7;
                const int m_loc = R & 127;
                __align__(16) __half hbuf[8];
                #pragma unroll
                for (int j = 0; j < 8; j++)
                    hbuf[j] = __float2half(Dsm[(2 * (lane8 * 8 + j) + h1) * 129 + m_loc]);
                const long long ob = cbz + (long long)(h1 * 2048 + n0 + m_loc) * ldc
                                   + (m0 >> 1) + lane8 * 8;
                *(uint4*)(Ch + ob) = *(uint4*)hbuf;
            }
        }
        return;
    }

    // direct epilogues (0/2)
    #pragma unroll
    for (int mi = 0; mi < 2; mi++) {
        #pragma unroll
        for (int j = 0; j < 8; j++) {
            const int row = m0 + wm + mi * 16 + g;
            const int col = n0 + wn + j * 8 + tg * 2;
            #pragma unroll
            for (int h = 0; h < 2; h++) {
                const long long idx = cbz + (long long)(row + h * 8) * ldc + col;
                const float d0 = acc[mi][j][h * 2];
                const float d1 = acc[mi][j][h * 2 + 1];
                if (EPI == 0) {
                    *(float2*)(C + idx) = make_float2(d0, d1);
                } else {
                    const float2 a = *(const float2*)(r1 + idx);
                    const float2 b = *(const float2*)(r2 + idx);
                    *(float2*)(C + idx) = make_float2(d0 + a.x + b.x, d1 + a.y + b.y);
                }
            }
        }
    }
}

// ---------------------------------------------------------------------------
// conversion kernels
// ---------------------------------------------------------------------------
// 4 weight splits in one launch: phi/theta/g -> W3 (contiguous), mask -> Wm
__global__ void __launch_bounds__(256) split4_kernel(
    const float* __restrict__ s0, const float* __restrict__ s1,
    const float* __restrict__ s2, const float* __restrict__ s3,
    __half* __restrict__ w3h, __half* __restrict__ w3l,
    __half* __restrict__ wmh, __half* __restrict__ wml)
{
    const int i = blockIdx.x * 256 + threadIdx.x;
    const int wsel = blockIdx.y;
    const float* s = (wsel == 0) ? s0 : (wsel == 1) ? s1 : (wsel == 2) ? s2 : s3;
    __half* hh = (wsel == 3) ? wmh : (w3h + wsel * CO * CH);
    __half* ll = (wsel == 3) ? wml : (w3l + wsel * CO * CH);
    __half h, l;
    hsplit(s[i], h, l);
    hh[i] = h; ll[i] = l;
}

// q,k,v: (b,512,4096) -> (b,4096,512) fp16 hi, z = 0..23.
// Tile 64c x 32x; half2 stores (128B per warp transaction).
__global__ void __launch_bounds__(256) tconv3_kernel(const float* __restrict__ q,
                                                     const float* __restrict__ k,
                                                     const float* __restrict__ v,
                                                     __half* __restrict__ oh) {
    __shared__ float T[64][33];
    const int z = blockIdx.z;
    const int b = z & 7;
    const float* src = (z < NB) ? q : (z < 2 * NB) ? k : v;
    const float* I = src + (size_t)b * CH * HW;
    const int tx = threadIdx.x & 31, ty = threadIdx.x >> 5;
    const int x0 = blockIdx.x * 32, c0 = blockIdx.y * 64;
    #pragma unroll
    for (int r = 0; r < 8; r++) {
        const int cl = r * 8 + ty;
        T[cl][tx] = I[(size_t)(c0 + cl) * HW + x0 + tx];
    }
    __syncthreads();
    const size_t ob = (size_t)z * HW * CH;
    #pragma unroll
    for (int p = 0; p < 4; p++) {
        const int xl = p * 8 + ty;
        const __half2 val = __halves2half2(__float2half(T[2 * tx][xl]),
                                           __float2half(T[2 * tx + 1][xl]));
        *(__half2*)(oh + ob + (size_t)(x0 + xl) * CH + c0 + 2 * tx) = val;
    }
}

// row softmax (rows of length 2048) -> fp16
__global__ void __launch_bounds__(256) softmax_h_kernel(const float* __restrict__ S,
                                                        __half* __restrict__ Sh) {
    const size_t row = blockIdx.x;
    const float* p = S + row * HW2;
    const int tid = threadIdx.x;

    float4 v0 = ((const float4*)p)[tid];
    float4 v1 = ((const float4*)p)[tid + 256];

    float mx = fmaxf(fmaxf(fmaxf(v0.x, v0.y), fmaxf(v0.z, v0.w)),
                     fmaxf(fmaxf(v1.x, v1.y), fmaxf(v1.z, v1.w)));
    __shared__ float red[8];
    #pragma unroll
    for (int o = 16; o > 0; o >>= 1) mx = fmaxf(mx, __shfl_xor_sync(0xffffffffu, mx, o));
    if ((tid & 31) == 0) red[tid >> 5] = mx;
    __syncthreads();
    mx = red[0];
    #pragma unroll
    for (int i = 1; i < 8; i++) mx = fmaxf(mx, red[i]);
    __syncthreads();

    v0.x = __expf(v0.x - mx); v0.y = __expf(v0.y - mx);
    v0.z = __expf(v0.z - mx); v0.w = __expf(v0.w - mx);
    v1.x = __expf(v1.x - mx); v1.y = __expf(v1.y - mx);
    v1.z = __expf(v1.z - mx); v1.w = __expf(v1.w - mx);

    float sum = v0.x + v0.y + v0.z + v0.w + v1.x + v1.y + v1.z + v1.w;
    #pragma unroll
    for (int o = 16; o > 0; o >>= 1) sum += __shfl_xor_sync(0xffffffffu, sum, o);
    if ((tid & 31) == 0) red[tid >> 5] = sum;
    __syncthreads();
    sum = red[0];
    #pragma unroll
    for (int i = 1; i < 8; i++) sum += red[i];

    const float inv = 1.0f / sum;
    __half2* ph = (__half2*)(Sh + row * HW2);
    ph[tid * 2 + 0] = __halves2half2(__float2half(v0.x * inv), __float2half(v0.y * inv));
    ph[tid * 2 + 1] = __halves2half2(__float2half(v0.z * inv), __float2half(v0.w * inv));
    ph[(tid + 256) * 2 + 0] = __halves2half2(__float2half(v1.x * inv), __float2half(v1.y * inv));
    ph[(tid + 256) * 2 + 1] = __halves2half2(__float2half(v1.z * inv), __float2half(v1.w * inv));
}

// ---------------------------------------------------------------------------
extern "C" void kernel_launch(void* const* d_in, const int* in_sizes, int n_in,
                              void* d_out, int out_size)
{
    const float* q    = (const float*)d_in[0];
    const float* k    = (const float*)d_in[1];
    const float* v    = (const float*)d_in[2];
    const float* Wphi = (const float*)d_in[3];
    const float* Wth  = (const float*)d_in[4];
    const float* Wg   = (const float*)d_in[5];
    const float* Wm   = (const float*)d_in[6];
    float* out = (float*)d_out;

    constexpr int SMEM = 98304;   // 3 stages x 32 KB stride (epilogue reuses)
    cudaFuncSetAttribute(mma_gemm<6,2>, cudaFuncAttributeMaxDynamicSharedMemorySize, SMEM);
    cudaFuncSetAttribute(mma_gemm<0,1>, cudaFuncAttributeMaxDynamicSharedMemorySize, SMEM);
    cudaFuncSetAttribute(mma_gemm<4,1>, cudaFuncAttributeMaxDynamicSharedMemorySize, SMEM);
    cudaFuncSetAttribute(mma_gemm<2,1>, cudaFuncAttributeMaxDynamicSharedMemorySize, SMEM);

    float* S;
    cudaGetSymbolAddress((void**)&S, g_S);
    __half *xTh, *Wmh, *Wml, *gh, *ptTh, *Sh, *y3h;
    cudaGetSymbolAddress((void**)&xTh, g_xTh);
    cudaGetSymbolAddress((void**)&Wmh, g_Wmh); cudaGetSymbolAddress((void**)&Wml, g_Wml);
    cudaGetSymbolAddress((void**)&gh, g_gh);
    cudaGetSymbolAddress((void**)&ptTh, g_ptTh);
    cudaGetSymbolAddress((void**)&Sh, g_Sh);
    cudaGetSymbolAddress((void**)&y3h, g_y3h);

    const dim3 blk(256);
    const long long sX  = (long long)CH * HW;    // q/k/v/out batch stride
    const long long sT  = (long long)HW * CH;    // xT per-z stride
    const long long sP  = (long long)CO * HW;    // g
    const long long sPT = (long long)HW2 * CH;   // pT/tT per-z stride
    const long long sS  = (long long)HW2 * HW2;  // scores
    const long long sY3 = (long long)HW * CO;    // y3

    __half* tTh = ptTh + (size_t)NB * sPT;

    // phi|theta|g weights contiguous in g_Sh head (unused until softmax)
    __half* W3h = Sh;                   // [3*CO*CH]
    __half* W3l = Sh + 3 * CO * CH;     // [3*CO*CH]

    // 0) weight splits (one launch)
    split4_kernel<<<dim3(CO * CH / 256, 4), blk>>>(Wphi, Wth, Wg, Wm,
                                                   W3h, W3l, Wmh, Wml);

    // 1) q/k/v transposes -> fp16 hi (one launch, half2 stores)
    tconv3_kernel<<<dim3(HW / 32, CH / 64, 3 * NB), blk>>>(q, k, v, xTh);

    // 2) TRIPLE conv: phi(2t, hi pT) | theta(2t, hi tT) | g(1t, row-major)
    mma_gemm<6,2><<<dim3(HW / 128, CO / 128, 3 * NB), blk, SMEM>>>(
        W3h, W3l, xTh, nullptr, ptTh, gh,
        CH, CH, 0, sT, sPT, nullptr, nullptr);

    // 3) scores (1-term): S[m,n] = sum_k' pTh[m,k'] * tTh[n,k']
    mma_gemm<0,1><<<dim3(HW2 / 128, HW2 / 128, NB), blk, SMEM>>>(
        ptTh, nullptr, tTh, S, nullptr, nullptr,
        CH, HW2, sPT, sPT, sS, nullptr, nullptr);

    // 4) row softmax -> fp16 (overwrites g_Sh head; weights already consumed)
    softmax_h_kernel<<<NB * HW2, blk>>>(S, Sh);

    // 5) attn apply (1-term, EPI=4): writes y3h transposed directly
    mma_gemm<4,1><<<dim3(HW2 / 128, CH / 128, NB), blk, SMEM>>>(
        gh, nullptr, Sh, nullptr, y3h, nullptr,
        HW2, CO, sP, sS, sY3, nullptr, nullptr);

    // 6) mask conv (1-term) + residual: out = Wm @ y3 + q + v
    mma_gemm<2,1><<<dim3(HW / 128, CH / 128, NB), blk, SMEM>>>(
        Wmh, nullptr, y3h, out, nullptr, nullptr,
        CO, HW, 0, sY3, sX, q, v);
}

// round 16
// speedup vs baseline: 1.4332x; 1.1232x over previous
#include <cuda_runtime.h>
#include <cuda_fp16.h>
#include <cstdint>

constexpr int NB  = 8;
constexpr int CH  = 512;
constexpr int HW  = 4096;
constexpr int HW2 = 2048;
constexpr int CO  = 256;

// ---------------- device scratch ----------------
__device__ __align__(256) float g_S [(size_t)NB * HW2 * HW2];

// q,k,v transposed fp16 hi, contiguous: [q(8) | k(8) | v(8)] each (4096,512)
__device__ __align__(256) __half g_xTh[(size_t)3 * NB * HW * CH];
__device__ __align__(256) __half g_W3h[3 * CO * CH];     // phi | theta | g weights (fp16)
__device__ __align__(256) __half g_Wmh[CH * CO];         // mask weights (fp16)
__device__ __align__(256) __half g_gh [(size_t)NB * CH * HW2];
// pT then tT contiguous: [pT(8) | tT(8)] each (2048,512), hi only
__device__ __align__(256) __half g_ptTh[(size_t)2 * NB * HW2 * CH];
__device__ __align__(256) __half g_Sh [(size_t)NB * HW2 * HW2];
__device__ __align__(256) __half g_y3h[(size_t)NB * HW * CO];

// ---------------- helpers ----------------
__device__ __forceinline__ uint32_t s2u(const void* p) {
    uint32_t a;
    asm("{ .reg .u64 t; cvta.to.shared.u64 t, %1; cvt.u32.u64 %0, t; }" : "=r"(a) : "l"(p));
    return a;
}
__device__ __forceinline__ void ldsm4(uint32_t* r, uint32_t addr) {
    asm volatile("ldmatrix.sync.aligned.m8n8.x4.shared.b16 {%0,%1,%2,%3}, [%4];"
                 : "=r"(r[0]), "=r"(r[1]), "=r"(r[2]), "=r"(r[3]) : "r"(addr));
}
__device__ __forceinline__ void mma16816(float* d, const uint32_t* a, uint32_t b0, uint32_t b1) {
    asm volatile("mma.sync.aligned.m16n8k16.row.col.f32.f16.f16.f32 "
                 "{%0,%1,%2,%3}, {%4,%5,%6,%7}, {%8,%9}, {%0,%1,%2,%3};"
                 : "+f"(d[0]), "+f"(d[1]), "+f"(d[2]), "+f"(d[3])
                 : "r"(a[0]), "r"(a[1]), "r"(a[2]), "r"(a[3]), "r"(b0), "r"(b1));
}
__device__ __forceinline__ void cpasync16(uint32_t s, const void* g) {
    asm volatile("cp.async.cg.shared.global [%0], [%1], 16;" :: "r"(s), "l"(g));
}
#define CP_COMMIT() asm volatile("cp.async.commit_group;" ::: "memory")
#define CP_WAIT1()  asm volatile("cp.async.wait_group 1;" ::: "memory")
#define CP_WAIT0()  asm volatile("cp.async.wait_group 0;" ::: "memory")

// smem per stage (16 KB stride): Ah @0, Bh @8192.
// Row = 64 B (32 fp16), chunk = 16 B, swizzle: chunk ^= (row>>1)&3
__device__ __forceinline__ void load_stage(uint32_t sbase,
    const __half* pAh, const __half* pBh,
    int Ktot, int kofs, int tid)
{
    const int row = tid >> 1;
    const int c0 = (tid & 1) * 2;
    const long long gofs = (long long)row * Ktot + kofs;
    #pragma unroll
    for (int s = 0; s < 2; s++) {
        const int c = c0 + s;
        const uint32_t soff = row * 64 + ((c ^ ((row >> 1) & 3)) << 4);
        cpasync16(sbase +        soff, pAh + gofs + c * 8);
        cpasync16(sbase + 8192 + soff, pBh + gofs + c * 8);
    }
}

// ---------------------------------------------------------------------------
// fp16 tensor-core GEMM (mma.sync), BK=32, 3-stage cp.async pipeline, 1-term.
// D(128x128 fp32 tile) = Ah(MxK) @ Bh^T(NxK), fp16 K-major.
// EPI: 0 fp32 store (scores)
//      2 fp32 + r1 + r2 residual (mask)
//      4 transposed hi store, parity-grouped cols (apply -> y3)
//      6 TRIPLE conv: z = 0..23, sel = z>>3. A = W3 + sel*CO*CH.
//        sel<2: transposed hi store (pT/tT). sel==2: row-major hi store to G.
// ---------------------------------------------------------------------------
template <int EPI>
__global__ void __launch_bounds__(256, 2) mma_gemm(
    const __half* __restrict__ Ah, const __half* __restrict__ Bh,
    float* __restrict__ C, __half* __restrict__ Ch, __half* __restrict__ G,
    int Ktot, int ldc,
    long long sA, long long sB, long long sC,
    const float* __restrict__ r1, const float* __restrict__ r2)
{
    extern __shared__ __align__(1024) char sm[];
    const int tid = threadIdx.x;
    const int wid = tid >> 5, lane = tid & 31;
    const uint32_t sb = s2u(sm);

    const int m0 = blockIdx.y * 128;
    const int n0 = blockIdx.x * 128;
    const long long bz = blockIdx.z;
    const int sel = (EPI == 6) ? (int)(bz >> 3) : 0;

    const __half* pAh = Ah + bz * sA + (long long)sel * CO * CH + (long long)m0 * Ktot;
    const __half* pBh = Bh + bz * sB + (long long)n0 * Ktot;

    const int wm = (wid >> 1) * 32;
    const int wn = (wid & 1) * 64;

    float acc[2][8][4];
    #pragma unroll
    for (int i = 0; i < 2; i++)
        #pragma unroll
        for (int j = 0; j < 8; j++)
            #pragma unroll
            for (int t = 0; t < 4; t++) acc[i][j][t] = 0.0f;

    const int nch = Ktot >> 5;
    load_stage(sb, pAh, pBh, Ktot, 0, tid);
    CP_COMMIT();
    load_stage(sb + 16384, pAh, pBh, Ktot, 32, tid);
    CP_COMMIT();

    uint32_t stage = 0;
    uint32_t nstage = 2;
    for (int ic = 0; ic < nch; ic++) {
        CP_WAIT1();
        __syncthreads();
        if (ic + 2 < nch) {
            load_stage(sb + nstage * 16384, pAh, pBh, Ktot, (ic + 2) << 5, tid);
        }
        CP_COMMIT();
        nstage = (nstage == 2) ? 0 : nstage + 1;

        const uint32_t st = sb + stage * 16384;
        stage = (stage == 2) ? 0 : stage + 1;
        #pragma unroll
        for (int kk = 0; kk < 32; kk += 16) {
            const int kc = (kk >> 3) + (lane >> 4);
            uint32_t a_h[2][4], b_all[4][4];
            #pragma unroll
            for (int mi = 0; mi < 2; mi++) {
                const int row = wm + mi * 16 + (lane & 15);
                const uint32_t ad = st + row * 64 + ((kc ^ ((row >> 1) & 3)) << 4);
                ldsm4(a_h[mi], ad);
            }
            #pragma unroll
            for (int jj = 0; jj < 4; jj++) {
                const int row = wn + jj * 16 + (lane & 15);
                const uint32_t bd = st + 8192 + row * 64 + ((kc ^ ((row >> 1) & 3)) << 4);
                ldsm4(b_all[jj], bd);
            }
            #pragma unroll
            for (int jj = 0; jj < 4; jj++)
                #pragma unroll
                for (int mi = 0; mi < 2; mi++) {
                    mma16816(acc[mi][jj * 2],     a_h[mi], b_all[jj][0], b_all[jj][2]);
                    mma16816(acc[mi][jj * 2 + 1], a_h[mi], b_all[jj][1], b_all[jj][3]);
                }
        }
    }

    const int g = lane >> 2, tg = lane & 3;

    if (EPI == 6 && sel == 2) {
        // g conv: row-major hi store, ld = HW, batch stride = CO*HW
        const long long gbz = (bz - 16) * (long long)CO * HW;
        #pragma unroll
        for (int mi = 0; mi < 2; mi++)
            #pragma unroll
            for (int j = 0; j < 8; j++) {
                const int row = m0 + wm + mi * 16 + g;
                const int col = n0 + wn + j * 8 + tg * 2;
                #pragma unroll
                for (int h = 0; h < 2; h++) {
                    const long long idx = gbz + (long long)(row + h * 8) * HW + col;
                    *(__half2*)(G + idx) = __halves2half2(
                        __float2half(acc[mi][j][h * 2]), __float2half(acc[mi][j][h * 2 + 1]));
                }
            }
        return;
    }

    const long long cbz = bz * sC;

    if (EPI == 6 || EPI == 4) {
        // stage tile fp32 in smem [row(m) * 129 + col(n)], transposed coalesced stores
        CP_WAIT0();
        __syncthreads();
        float* Dsm = (float*)sm;
        #pragma unroll
        for (int mi = 0; mi < 2; mi++)
            #pragma unroll
            for (int j = 0; j < 8; j++)
                #pragma unroll
                for (int h = 0; h < 2; h++) {
                    const int row = wm + mi * 16 + g + h * 8;
                    const int col = wn + j * 8 + tg * 2;
                    Dsm[row * 129 + col]     = acc[mi][j][h * 2];
                    Dsm[row * 129 + col + 1] = acc[mi][j][h * 2 + 1];
                }
        __syncthreads();

        if (EPI == 6) {
            // pT/tT: out[n][h1*256 + o] HI; row = 128 fp16 = 256B = 16 lanes x 16B.
            const int h1 = n0 >> 11;
            const int xb = n0 & 2047;
            const int lane16 = lane & 15;
            const int sub = lane >> 4;                 // 2 rows per warp per pass
            #pragma unroll
            for (int p = 0; p < 8; p++) {
                const int n_loc = p * 16 + wid * 2 + sub;
                __align__(16) __half hbuf[8];
                #pragma unroll
                for (int j = 0; j < 8; j++)
                    hbuf[j] = __float2half(Dsm[(lane16 * 8 + j) * 129 + n_loc]);
                const long long ob = cbz + (long long)(xb + n_loc) * ldc
                                   + h1 * 256 + m0 + lane16 * 8;
                *(uint4*)(Ch + ob) = *(uint4*)hbuf;
            }
        } else {
            // y3[h1*2048 + n0 + m][m0/2 + o2]; row = 64 fp16 = 128B = 8 lanes x 16B.
            const int lane8 = lane & 7;
            const int rsub = lane >> 3;                // 4 rows per warp per pass
            #pragma unroll
            for (int p = 0; p < 8; p++) {
                const int R = p * 32 + wid * 4 + rsub; // 0..255
                const int h1 = R >> 7;
                const int m_loc = R & 127;
                __align__(16) __half hbuf[8];
                #pragma unroll
                for (int j = 0; j < 8; j++)
                    hbuf[j] = __float2half(Dsm[(2 * (lane8 * 8 + j) + h1) * 129 + m_loc]);
                const long long ob = cbz + (long long)(h1 * 2048 + n0 + m_loc) * ldc
                                   + (m0 >> 1) + lane8 * 8;
                *(uint4*)(Ch + ob) = *(uint4*)hbuf;
            }
        }
        return;
    }

    // direct epilogues (0/2)
    #pragma unroll
    for (int mi = 0; mi < 2; mi++) {
        #pragma unroll
        for (int j = 0; j < 8; j++) {
            const int row = m0 + wm + mi * 16 + g;
            const int col = n0 + wn + j * 8 + tg * 2;
            #pragma unroll
            for (int h = 0; h < 2; h++) {
                const long long idx = cbz + (long long)(row + h * 8) * ldc + col;
                const float d0 = acc[mi][j][h * 2];
                const float d1 = acc[mi][j][h * 2 + 1];
                if (EPI == 0) {
                    *(float2*)(C + idx) = make_float2(d0, d1);
                } else {
                    const float2 a = *(const float2*)(r1 + idx);
                    const float2 b = *(const float2*)(r2 + idx);
                    *(float2*)(C + idx) = make_float2(d0 + a.x + b.x, d1 + a.y + b.y);
                }
            }
        }
    }
}

// ---------------------------------------------------------------------------
// conversion kernels
// ---------------------------------------------------------------------------
// fp32 -> fp16 for all 4 weight tensors (one launch)
__global__ void __launch_bounds__(256) wconv_kernel(
    const float* __restrict__ s0, const float* __restrict__ s1,
    const float* __restrict__ s2, const float* __restrict__ s3,
    __half* __restrict__ w3h, __half* __restrict__ wmh)
{
    const int i = blockIdx.x * 256 + threadIdx.x;
    const int wsel = blockIdx.y;
    const float* s = (wsel == 0) ? s0 : (wsel == 1) ? s1 : (wsel == 2) ? s2 : s3;
    __half* dst = (wsel == 3) ? wmh : (w3h + wsel * CO * CH);
    dst[i] = __float2half(s[i]);
}

// q,k,v: (b,512,4096) -> (b,4096,512) fp16 hi, z = 0..23.
// Tile 64c x 32x; half2 stores (128B per warp transaction).
__global__ void __launch_bounds__(256) tconv3_kernel(const float* __restrict__ q,
                                                     const float* __restrict__ k,
                                                     const float* __restrict__ v,
                                                     __half* __restrict__ oh) {
    __shared__ float T[64][33];
    const int z = blockIdx.z;
    const int b = z & 7;
    const float* src = (z < NB) ? q : (z < 2 * NB) ? k : v;
    const float* I = src + (size_t)b * CH * HW;
    const int tx = threadIdx.x & 31, ty = threadIdx.x >> 5;
    const int x0 = blockIdx.x * 32, c0 = blockIdx.y * 64;
    #pragma unroll
    for (int r = 0; r < 8; r++) {
        const int cl = r * 8 + ty;
        T[cl][tx] = I[(size_t)(c0 + cl) * HW + x0 + tx];
    }
    __syncthreads();
    const size_t ob = (size_t)z * HW * CH;
    #pragma unroll
    for (int p = 0; p < 4; p++) {
        const int xl = p * 8 + ty;
        const __half2 val = __halves2half2(__float2half(T[2 * tx][xl]),
                                           __float2half(T[2 * tx + 1][xl]));
        *(__half2*)(oh + ob + (size_t)(x0 + xl) * CH + c0 + 2 * tx) = val;
    }
}

// row softmax (rows of length 2048) -> fp16
__global__ void __launch_bounds__(256) softmax_h_kernel(const float* __restrict__ S,
                                                        __half* __restrict__ Sh) {
    const size_t row = blockIdx.x;
    const float* p = S + row * HW2;
    const int tid = threadIdx.x;

    float4 v0 = ((const float4*)p)[tid];
    float4 v1 = ((const float4*)p)[tid + 256];

    float mx = fmaxf(fmaxf(fmaxf(v0.x, v0.y), fmaxf(v0.z, v0.w)),
                     fmaxf(fmaxf(v1.x, v1.y), fmaxf(v1.z, v1.w)));
    __shared__ float red[8];
    #pragma unroll
    for (int o = 16; o > 0; o >>= 1) mx = fmaxf(mx, __shfl_xor_sync(0xffffffffu, mx, o));
    if ((tid & 31) == 0) red[tid >> 5] = mx;
    __syncthreads();
    mx = red[0];
    #pragma unroll
    for (int i = 1; i < 8; i++) mx = fmaxf(mx, red[i]);
    __syncthreads();

    v0.x = __expf(v0.x - mx); v0.y = __expf(v0.y - mx);
    v0.z = __expf(v0.z - mx); v0.w = __expf(v0.w - mx);
    v1.x = __expf(v1.x - mx); v1.y = __expf(v1.y - mx);
    v1.z = __expf(v1.z - mx); v1.w = __expf(v1.w - mx);

    float sum = v0.x + v0.y + v0.z + v0.w + v1.x + v1.y + v1.z + v1.w;
    #pragma unroll
    for (int o = 16; o > 0; o >>= 1) sum += __shfl_xor_sync(0xffffffffu, sum, o);
    if ((tid & 31) == 0) red[tid >> 5] = sum;
    __syncthreads();
    sum = red[0];
    #pragma unroll
    for (int i = 1; i < 8; i++) sum += red[i];

    const float inv = 1.0f / sum;
    __half2* ph = (__half2*)(Sh + row * HW2);
    ph[tid * 2 + 0] = __halves2half2(__float2half(v0.x * inv), __float2half(v0.y * inv));
    ph[tid * 2 + 1] = __halves2half2(__float2half(v0.z * inv), __float2half(v0.w * inv));
    ph[(tid + 256) * 2 + 0] = __halves2half2(__float2half(v1.x * inv), __float2half(v1.y * inv));
    ph[(tid + 256) * 2 + 1] = __halves2half2(__float2half(v1.z * inv), __float2half(v1.w * inv));
}

// ---------------------------------------------------------------------------
extern "C" void kernel_launch(void* const* d_in, const int* in_sizes, int n_in,
                              void* d_out, int out_size)
{
    const float* q    = (const float*)d_in[0];
    const float* k    = (const float*)d_in[1];
    const float* v    = (const float*)d_in[2];
    const float* Wphi = (const float*)d_in[3];
    const float* Wth  = (const float*)d_in[4];
    const float* Wg   = (const float*)d_in[5];
    const float* Wm   = (const float*)d_in[6];
    float* out = (float*)d_out;

    // mainloop: 3 x 16 KB stages; EPI 6/4 epilogue needs 128*129*4 = 66048 B
    constexpr int SMEM_MAIN = 49152;
    constexpr int SMEM_EPI  = 66560;
    cudaFuncSetAttribute(mma_gemm<6>, cudaFuncAttributeMaxDynamicSharedMemorySize, SMEM_EPI);
    cudaFuncSetAttribute(mma_gemm<0>, cudaFuncAttributeMaxDynamicSharedMemorySize, SMEM_MAIN);
    cudaFuncSetAttribute(mma_gemm<4>, cudaFuncAttributeMaxDynamicSharedMemorySize, SMEM_EPI);
    cudaFuncSetAttribute(mma_gemm<2>, cudaFuncAttributeMaxDynamicSharedMemorySize, SMEM_MAIN);

    float* S;
    cudaGetSymbolAddress((void**)&S, g_S);
    __half *xTh, *W3h, *Wmh, *gh, *ptTh, *Sh, *y3h;
    cudaGetSymbolAddress((void**)&xTh, g_xTh);
    cudaGetSymbolAddress((void**)&W3h, g_W3h);
    cudaGetSymbolAddress((void**)&Wmh, g_Wmh);
    cudaGetSymbolAddress((void**)&gh, g_gh);
    cudaGetSymbolAddress((void**)&ptTh, g_ptTh);
    cudaGetSymbolAddress((void**)&Sh, g_Sh);
    cudaGetSymbolAddress((void**)&y3h, g_y3h);

    const dim3 blk(256);
    const long long sX  = (long long)CH * HW;    // q/k/v/out batch stride
    const long long sT  = (long long)HW * CH;    // xT per-z stride
    const long long sP  = (long long)CO * HW;    // g
    const long long sPT = (long long)HW2 * CH;   // pT/tT per-z stride
    const long long sS  = (long long)HW2 * HW2;  // scores
    const long long sY3 = (long long)HW * CO;    // y3

    __half* tTh = ptTh + (size_t)NB * sPT;

    // 0) weight conversions (one launch)
    wconv_kernel<<<dim3(CO * CH / 256, 4), blk>>>(Wphi, Wth, Wg, Wm, W3h, Wmh);

    // 1) q/k/v transposes -> fp16 hi (one launch, half2 stores)
    tconv3_kernel<<<dim3(HW / 32, CH / 64, 3 * NB), blk>>>(q, k, v, xTh);

    // 2) TRIPLE conv (all 1-term): phi -> pT | theta -> tT | g -> row-major
    mma_gemm<6><<<dim3(HW / 128, CO / 128, 3 * NB), blk, SMEM_EPI>>>(
        W3h, xTh, nullptr, ptTh, gh,
        CH, CH, 0, sT, sPT, nullptr, nullptr);

    // 3) scores (1-term): S[m,n] = sum_k' pTh[m,k'] * tTh[n,k']
    mma_gemm<0><<<dim3(HW2 / 128, HW2 / 128, NB), blk, SMEM_MAIN>>>(
        ptTh, tTh, S, nullptr, nullptr,
        CH, HW2, sPT, sPT, sS, nullptr, nullptr);

    // 4) row softmax -> fp16
    softmax_h_kernel<<<NB * HW2, blk>>>(S, Sh);

    // 5) attn apply (1-term, EPI=4): writes y3h transposed directly
    mma_gemm<4><<<dim3(HW2 / 128, CH / 128, NB), blk, SMEM_EPI>>>(
        gh, Sh, nullptr, y3h, nullptr,
        HW2, CO, sP, sS, sY3, nullptr, nullptr);

    // 6) mask conv (1-term) + residual: out = Wm @ y3 + q + v
    mma_gemm<2><<<dim3(HW / 128, CH / 128, NB), blk, SMEM_MAIN>>>(
        Wmh, y3h, out, nullptr, nullptr,
        CO, HW, 0, sY3, sX, q, v);
}